// round 11
// baseline (speedup 1.0000x reference)
#include <cuda_runtime.h>
#include <cuda_bf16.h>
#include <math.h>
#include <stdint.h>

typedef __nv_bfloat16 bf16;

#define LLAYERS 6
#define DMODEL  512
#define NH      8
#define HD      64
#define NVOCAB  10000
#define NB      32
#define NS      64
#define NNR     196
#define NTOK    (NB*NS)     // 2048
#define NCTOK   (NB*NNR)    // 6272
#define WSZ     ((size_t)DMODEL*DMODEL)
#define CSZ     ((size_t)NCTOK*DMODEL)

// ================= scratch =================
__device__ bf16  g_actH[NTOK*DMODEL], g_actL[NTOK*DMODEL];
__device__ float g_q[NTOK*DMODEL], g_k[NTOK*DMODEL], g_v[NTOK*DMODEL];
__device__ bf16  g_aoH[NTOK*DMODEL], g_aoL[NTOK*DMODEL];
__device__ float g_kc[LLAYERS][CSZ], g_vc[LLAYERS][CSZ];
__device__ float g_gq[LLAYERS][NB*DMODEL];
__device__ bf16  g_KinH[CSZ], g_KinL[CSZ], g_VinH[CSZ], g_VinL[CSZ];
__device__ bf16  g_gH[NB*DMODEL], g_gL[NB*DMODEL];
__device__ bf16  g_wTH[9*LLAYERS*WSZ], g_wTL[9*LLAYERS*WSZ];   // [N,K] transposed
__device__ bf16  g_wfTH[(size_t)NVOCAB*DMODEL], g_wfTL[(size_t)NVOCAB*DMODEL];

// ================= helpers =================
__device__ __forceinline__ uint32_t smem_to_u32(const void* p) {
    uint32_t a;
    asm("{ .reg .u64 t; cvta.to.shared.u64 t, %1; cvt.u32.u64 %0, t; }" : "=r"(a) : "l"(p));
    return a;
}
__device__ __forceinline__ void cp16(uint32_t dst, const void* src, bool p) {
    int sz = p ? 16 : 0;
    asm volatile("cp.async.cg.shared.global [%0], [%1], 16, %2;" :: "r"(dst), "l"(src), "r"(sz) : "memory");
}
#define CP_COMMIT() asm volatile("cp.async.commit_group;" ::: "memory")
#define CP_WAIT0()  asm volatile("cp.async.wait_group 0;" ::: "memory")
#define CP_WAIT1()  asm volatile("cp.async.wait_group 1;" ::: "memory")

__device__ __forceinline__ void ldm4(uint32_t addr, uint32_t* r) {
    asm volatile("ldmatrix.sync.aligned.m8n8.x4.shared.b16 {%0,%1,%2,%3}, [%4];"
        : "=r"(r[0]), "=r"(r[1]), "=r"(r[2]), "=r"(r[3]) : "r"(addr));
}
__device__ __forceinline__ void mma16816(float* c, const uint32_t* a, uint32_t b0, uint32_t b1) {
    asm volatile("mma.sync.aligned.m16n8k16.row.col.f32.bf16.bf16.f32 "
        "{%0,%1,%2,%3}, {%4,%5,%6,%7}, {%8,%9}, {%0,%1,%2,%3};"
        : "+f"(c[0]), "+f"(c[1]), "+f"(c[2]), "+f"(c[3])
        : "r"(a[0]), "r"(a[1]), "r"(a[2]), "r"(a[3]), "r"(b0), "r"(b1));
}
__device__ __forceinline__ void split2(float v, bf16& h, bf16& l) {
    h = __float2bfloat16(v);
    l = __float2bfloat16(v - __bfloat162float(h));
}

// ================= conversion kernels =================
union BPack { bf16 b[4]; uint2 u; };

__global__ void split_kernel(const float* __restrict__ src, bf16* __restrict__ h,
                             bf16* __restrict__ l, int n) {
    int i = (blockIdx.x * blockDim.x + threadIdx.x) * 4;
    if (i < n) {
        float4 v = *(const float4*)(src + i);
        BPack ph, pl;
        split2(v.x, ph.b[0], pl.b[0]);
        split2(v.y, ph.b[1], pl.b[1]);
        split2(v.z, ph.b[2], pl.b[2]);
        split2(v.w, ph.b[3], pl.b[3]);
        *(uint2*)(h + i) = ph.u;
        *(uint2*)(l + i) = pl.u;
    }
}

struct WPtrs { const float* p[9]; };

__global__ void wconv_all_kernel(WPtrs wp, bf16* __restrict__ Th, bf16* __restrict__ Tl) {
    __shared__ float t[32][33];
    const int z = blockIdx.z, m = z / LLAYERS, l = z % LLAYERS;
    const float* Wz = wp.p[m] + (size_t)l * WSZ;
    bf16* Thz = Th + ((size_t)m*LLAYERS + l) * WSZ;
    bf16* Tlz = Tl + ((size_t)m*LLAYERS + l) * WSZ;
    int n0 = blockIdx.x * 32, k0 = blockIdx.y * 32;
    int tx = threadIdx.x, ty = threadIdx.y;
    for (int r = ty; r < 32; r += 8) {
        t[r][tx] = Wz[(size_t)(k0 + r) * DMODEL + n0 + tx];
    }
    __syncthreads();
    for (int r = ty; r < 32; r += 8) {
        bf16 hh, ll; split2(t[tx][r], hh, ll);
        Thz[(size_t)(n0 + r) * DMODEL + k0 + tx] = hh;
        Tlz[(size_t)(n0 + r) * DMODEL + k0 + tx] = ll;
    }
}

__global__ void wconv_kernel(const float* __restrict__ W, bf16* __restrict__ Th,
                             bf16* __restrict__ Tl, int Kdim, int Ndim) {
    __shared__ float t[32][33];
    int n0 = blockIdx.x * 32, k0 = blockIdx.y * 32;
    int tx = threadIdx.x, ty = threadIdx.y;
    for (int r = ty; r < 32; r += 8) {
        int n = n0 + tx;
        t[r][tx] = (n < Ndim) ? W[(size_t)(k0 + r) * Ndim + n] : 0.f;
    }
    __syncthreads();
    for (int r = ty; r < 32; r += 8) {
        int n = n0 + r;
        if (n < Ndim) {
            bf16 hh, ll; split2(t[tx][r], hh, ll);
            Th[(size_t)n * Kdim + k0 + tx] = hh;
            Tl[(size_t)n * Kdim + k0 + tx] = ll;
        }
    }
}

// ================= embedding + positional encoding =================
__global__ void embed_kernel(const int* __restrict__ x, const float* __restrict__ emb,
                             bf16* __restrict__ outH, bf16* __restrict__ outL) {
    int t = blockIdx.x;
    int s = t % NS;
    int tok = x[t];
    for (int d = threadIdx.x; d < DMODEL; d += blockDim.x) {
        int j = d >> 1;
        float ang = (float)s * powf(10000.0f, -(2.0f*(float)j)/(float)DMODEL);
        float pe = (d & 1) ? cosf(ang) : sinf(ang);
        float v = emb[tok*DMODEL + d] + pe;
        bf16 hh, ll; split2(v, hh, ll);
        outH[t*DMODEL + d] = hh; outL[t*DMODEL + d] = ll;
    }
}

// ================= split-bf16 HMMA GEMM (generalized tiles) =================
#define NCHUNK   16                       // 512/32
#define STRIDE   40                       // 32 + 8 pad
template<int MT, int NT, int STAGES, int THREADS> struct TileCfg {
    static const int TA  = MT*STRIDE*2;
    static const int TB  = NT*STRIDE*2;
    static const int BUF = 2*TA + 2*TB;
    static const int SMEM = STAGES*BUF;
    static const int NW  = THREADS/32;
    static const int MW  = MT/32;
    static const int NWN = NW/MW;
    static const int NP  = NT/(16*NWN);
};

template<int MT, int NT, int STAGES, int THREADS>
__device__ __forceinline__ void load_tiles(
    const bf16* __restrict__ Ah, const bf16* __restrict__ Al,
    const bf16* __restrict__ Bh, const bf16* __restrict__ Bl,
    int M, int N, int m0, int n0, int ch, uint32_t sbuf, int tid)
{
    typedef TileCfg<MT, NT, STAGES, THREADS> TC;
    // A: MT rows, THREADS == 2*MT -> 2 threads/row, 2 cp16/matrix
    {
        const int row = tid >> 1;
        const int qd  = (tid & 1) * 2;
        const uint32_t sof = sbuf + (uint32_t)(row*STRIDE + qd*8) * 2;
        bool ok = (m0 + row) < M;
        const bf16* pa = Ah + (size_t)(m0 + row) * 512 + ch*32 + qd*8;
        const bf16* pl = Al + (size_t)(m0 + row) * 512 + ch*32 + qd*8;
        cp16(sof,               pa,     ok);
        cp16(sof + 16,          pa + 8, ok);
        cp16(sof + TC::TA,      pl,     ok);
        cp16(sof + TC::TA + 16, pl + 8, ok);
    }
    if (NT * 2 == THREADS) {
        const int row = tid >> 1;
        const int qd  = (tid & 1) * 2;
        const uint32_t sof = sbuf + 2*TC::TA + (uint32_t)(row*STRIDE + qd*8) * 2;
        bool ok = (n0 + row) < N;
        const bf16* pb = Bh + (size_t)(n0 + row) * 512 + ch*32 + qd*8;
        const bf16* pl = Bl + (size_t)(n0 + row) * 512 + ch*32 + qd*8;
        cp16(sof,               pb,     ok);
        cp16(sof + 16,          pb + 8, ok);
        cp16(sof + TC::TB,      pl,     ok);
        cp16(sof + TC::TB + 16, pl + 8, ok);
    } else {
        const int row = tid >> 2;               // NT*4 == THREADS
        const int qd  = tid & 3;
        const uint32_t sof = sbuf + 2*TC::TA + (uint32_t)(row*STRIDE + qd*8) * 2;
        bool ok = (n0 + row) < N;
        cp16(sof,            Bh + (size_t)(n0 + row) * 512 + ch*32 + qd*8, ok);
        cp16(sof + TC::TB,   Bl + (size_t)(n0 + row) * 512 + ch*32 + qd*8, ok);
    }
}

template<int MT, int NT, int STAGES, int THREADS>
__device__ void gemm_core(const bf16* __restrict__ Ah, const bf16* __restrict__ Al,
                          const bf16* __restrict__ Bh, const bf16* __restrict__ Bl,
                          float* __restrict__ C, bf16* __restrict__ Ch, bf16* __restrict__ Cl,
                          int M, int N,
                          const float* __restrict__ rowBias, const float* __restrict__ colBias)
{
    typedef TileCfg<MT, NT, STAGES, THREADS> TC;
    extern __shared__ char smem[];
    const uint32_t sb = smem_to_u32(smem);
    const int tid = threadIdx.x, wid = tid >> 5, lane = tid & 31;
    const int wm = wid % TC::MW, wn = wid / TC::MW;
    const int m0 = blockIdx.y * MT, n0 = blockIdx.x * NT;
    const int NP = TC::NP;
    const int BUF = TC::BUF;
    const int WNW = NT / TC::NWN;      // n-width per warp

    float acc[2][2*TC::NP][4];
    #pragma unroll
    for (int i = 0; i < 2; i++)
        #pragma unroll
        for (int j = 0; j < 2*NP; j++)
            #pragma unroll
            for (int e = 0; e < 4; e++) acc[i][j][e] = 0.f;

    #pragma unroll
    for (int s = 0; s < STAGES-1; s++) {
        load_tiles<MT, NT, STAGES, THREADS>(Ah, Al, Bh, Bl, M, N, m0, n0, s, sb + s*BUF, tid);
        CP_COMMIT();
    }

    int cur = 0;
    const int aRow = (lane & 15);
    const int aCol = (lane >> 4) << 3;
    const int bRow = (lane & 7) + (((lane >> 4) & 1) << 3);
    const int bCol = ((lane >> 3) & 1) << 3;

    #pragma unroll 1
    for (int ch = 0; ch < NCHUNK; ch++) {
        if (STAGES == 3 && ch < NCHUNK-1) { CP_WAIT1(); } else { CP_WAIT0(); }
        __syncthreads();
        if (ch + STAGES - 1 < NCHUNK) {
            int nb = cur + STAGES - 1; if (nb >= STAGES) nb -= STAGES;
            load_tiles<MT, NT, STAGES, THREADS>(Ah, Al, Bh, Bl, M, N, m0, n0, ch + STAGES - 1, sb + nb*BUF, tid);
            CP_COMMIT();
        }
        const uint32_t sAh = sb + cur*BUF;
        const uint32_t sAl = sAh + TC::TA;
        const uint32_t sBh = sAh + 2*TC::TA;
        const uint32_t sBl = sBh + TC::TB;

        #pragma unroll
        for (int k16 = 0; k16 < 32; k16 += 16) {
            uint32_t ah[8], al[8];
            uint32_t bh[TC::NP][4], bl[TC::NP][4];
            {
                uint32_t a0 = (uint32_t)((wm*32 + aRow)*STRIDE + k16 + aCol) * 2;
                uint32_t a1 = (uint32_t)((wm*32 + 16 + aRow)*STRIDE + k16 + aCol) * 2;
                ldm4(sAh + a0, ah);  ldm4(sAh + a1, ah + 4);
                ldm4(sAl + a0, al);  ldm4(sAl + a1, al + 4);
            }
            #pragma unroll
            for (int np = 0; np < NP; np++) {
                const int nb2 = wn*WNW + np*16;
                const uint32_t boff = (uint32_t)((nb2 + bRow)*STRIDE + k16 + bCol) * 2;
                ldm4(sBh + boff, bh[np]);
                ldm4(sBl + boff, bl[np]);
            }
            // term 1: Ah x Bh
            #pragma unroll
            for (int np = 0; np < NP; np++)
                #pragma unroll
                for (int mi = 0; mi < 2; mi++) {
                    mma16816(acc[mi][np*2],     ah + 4*mi, bh[np][0], bh[np][1]);
                    mma16816(acc[mi][np*2 + 1], ah + 4*mi, bh[np][2], bh[np][3]);
                }
            // term 2: Ah x Bl
            #pragma unroll
            for (int np = 0; np < NP; np++)
                #pragma unroll
                for (int mi = 0; mi < 2; mi++) {
                    mma16816(acc[mi][np*2],     ah + 4*mi, bl[np][0], bl[np][1]);
                    mma16816(acc[mi][np*2 + 1], ah + 4*mi, bl[np][2], bl[np][3]);
                }
            // term 3: Al x Bh
            #pragma unroll
            for (int np = 0; np < NP; np++)
                #pragma unroll
                for (int mi = 0; mi < 2; mi++) {
                    mma16816(acc[mi][np*2],     al + 4*mi, bh[np][0], bh[np][1]);
                    mma16816(acc[mi][np*2 + 1], al + 4*mi, bh[np][2], bh[np][3]);
                }
        }
        cur++; if (cur == STAGES) cur = 0;
    }

    // epilogue
    const int r0 = m0 + wm*32 + (lane >> 2);
    const int c0 = n0 + wn*WNW + (lane & 3) * 2;
    #pragma unroll
    for (int mi = 0; mi < 2; mi++) {
        #pragma unroll
        for (int na = 0; na < 2*NP; na++) {
            const int col = c0 + (na >> 1)*16 + (na & 1)*8;
            #pragma unroll
            for (int e = 0; e < 4; e++) {
                const int r = r0 + mi*16 + ((e >> 1) << 3);
                const int c = col + (e & 1);
                if (r >= M || c >= N) continue;
                float v = acc[mi][na][e];
                if (rowBias) v += rowBias[(size_t)(r >> 6) * N + c];
                if (colBias) v += colBias[c];
                if (C) C[(size_t)r * N + c] = v;
                if (Ch) {
                    bf16 hh, ll; split2(v, hh, ll);
                    Ch[(size_t)r * N + c] = hh;
                    Cl[(size_t)r * N + c] = ll;
                }
            }
        }
    }
}

#define SMEM64S (TileCfg<64,64,3,128>::SMEM)    // 61440 B
#define SMEM64  (TileCfg<128,64,3,256>::SMEM)   // 92160 B
#define SMEM128 (TileCfg<128,128,2,256>::SMEM)  // 81920 B

// small-tile GEMM for per-layer activation GEMMs: grid (8, 32) = 256 CTAs
__global__ void __launch_bounds__(128, 3) gemm_plain64s(
    const bf16* Ah, const bf16* Al, const bf16* Bh, const bf16* Bl,
    float* C, bf16* Ch, bf16* Cl, int M, int N,
    const float* rowBias, const float* colBias) {
    gemm_core<64,64,3,128>(Ah, Al, Bh, Bl, C, Ch, Cl, M, N, rowBias, colBias);
}

__global__ void __launch_bounds__(256, 2) gemm_final128(
    const bf16* Ah, const bf16* Al, const bf16* Bh, const bf16* Bl,
    float* C, int M, int N, const float* colBias) {
    gemm_core<128,128,2,256>(Ah, Al, Bh, Bl, C, nullptr, nullptr, M, N, nullptr, colBias);
}

__global__ void __launch_bounds__(256, 2) gemm_qkv3(
    const bf16* Ah, const bf16* Al, const bf16* wTH, const bf16* wTL, int l,
    float* q, float* k, float* v) {
    const int z = blockIdx.z;
    const size_t off = ((size_t)z*LLAYERS + l) * WSZ;
    float* C = (z == 0) ? q : (z == 1) ? k : v;
    gemm_core<128,64,3,256>(Ah, Al, wTH + off, wTL + off, C, nullptr, nullptr, NTOK, DMODEL, nullptr, nullptr);
}

// per-layer cross K/V projection (runs on aux stream)
__global__ void __launch_bounds__(256, 2) gemm_cross2(
    const bf16* KinH, const bf16* KinL, const bf16* VinH, const bf16* VinL,
    const bf16* wTH, const bf16* wTL, int l, float* kc, float* vc) {
    const int kv = blockIdx.z;
    const size_t woff = ((size_t)(6 + kv)*LLAYERS + l) * WSZ;
    gemm_core<128,128,2,256>(kv ? VinH : KinH, kv ? VinL : KinL, wTH + woff, wTL + woff,
                             kv ? vc : kc, nullptr, nullptr, NCTOK, DMODEL, nullptr, nullptr);
}

__global__ void __launch_bounds__(256, 2) gemm_gq6(
    const bf16* gH, const bf16* gL, const bf16* wTH, const bf16* wTL, float* gq) {
    const int l = blockIdx.z;
    const size_t woff = ((size_t)5*LLAYERS + l) * WSZ;
    gemm_core<128,64,3,256>(gH, gL, wTH + woff, wTL + woff,
                            gq + (size_t)l*NB*DMODEL, nullptr, nullptr, NB, DMODEL, nullptr, nullptr);
}

// ================= fused attention (fp32, register-blocked), writes hi/lo ======
#define ATTN_SMEM_FLOATS (3*64*65 + 8*512)
template<bool CAUSAL>
__global__ void attn_kernel(const float* __restrict__ Q, const float* __restrict__ Kb,
                            const float* __restrict__ Vb,
                            bf16* __restrict__ Oh, bf16* __restrict__ Ol,
                            int skeys, int kvTokens) {
    extern __shared__ float sm[];
    float* Qs = sm;
    float* Ks = sm + 64*65;
    float* Vs = sm + 2*64*65;
    float* Ps = sm + 3*64*65;

    const int b = blockIdx.x / NH, h = blockIdx.x % NH;
    const int tid = threadIdx.x, w = tid >> 5, lane = tid & 31;

    for (int i = tid; i < 64*64; i += 256) {
        int r = i >> 6, c = i & 63;
        Qs[r*65 + c] = Q[(size_t)(b*NS + r)*DMODEL + h*HD + c];
    }
    float mrow[8], lrow[8], a0[8], a1[8];
    #pragma unroll
    for (int i = 0; i < 8; i++) { mrow[i] = -1e30f; lrow[i] = 0.f; a0[i] = 0.f; a1[i] = 0.f; }
    __syncthreads();

    const int nch = (skeys + 63) >> 6;
    for (int ch = 0; ch < nch; ch++) {
        const int kb = ch * 64;
        const int cnt = min(64, skeys - kb);
        for (int i = tid; i < 64*64; i += 256) {
            int r = i >> 6, c = i & 63;
            float kv = 0.f, vv = 0.f;
            if (r < cnt) {
                size_t off = (size_t)(b*kvTokens + kb + r)*DMODEL + h*HD + c;
                kv = Kb[off]; vv = Vb[off];
            }
            Ks[r*65 + c] = kv; Vs[r*65 + c] = vv;
        }
        __syncthreads();

        float d0[8], d1[8];
        #pragma unroll
        for (int i = 0; i < 8; i++) { d0[i] = 0.f; d1[i] = 0.f; }
        #pragma unroll 4
        for (int d = 0; d < 64; d++) {
            float k0 = Ks[lane*65 + d];
            float k1 = Ks[(lane+32)*65 + d];
            #pragma unroll
            for (int rr = 0; rr < 8; rr++) {
                float qv = Qs[(w*8 + rr)*65 + d];
                d0[rr] += qv * k0;
                d1[rr] += qv * k1;
            }
        }

        #pragma unroll
        for (int rr = 0; rr < 8; rr++) {
            const int r = w*8 + rr;
            float s0 = d0[rr] * 0.125f, s1 = d1[rr] * 0.125f;
            bool v0 = (lane      < cnt) && (!CAUSAL || (kb + lane)      <= r);
            bool v1 = (lane + 32 < cnt) && (!CAUSAL || (kb + lane + 32) <= r);
            if (!v0) s0 = -1e30f;
            if (!v1) s1 = -1e30f;
            float cm = fmaxf(s0, s1);
            #pragma unroll
            for (int o = 16; o > 0; o >>= 1) cm = fmaxf(cm, __shfl_xor_sync(0xffffffffu, cm, o));
            float nm = fmaxf(mrow[rr], cm);
            float corr = __expf(mrow[rr] - nm);
            float p0 = v0 ? __expf(s0 - nm) : 0.f;
            float p1 = v1 ? __expf(s1 - nm) : 0.f;
            float ps = p0 + p1;
            #pragma unroll
            for (int o = 16; o > 0; o >>= 1) ps += __shfl_xor_sync(0xffffffffu, ps, o);
            lrow[rr] = lrow[rr]*corr + ps;
            mrow[rr] = nm;
            a0[rr] *= corr; a1[rr] *= corr;
            Ps[w*512 + rr*64 + lane]      = p0;
            Ps[w*512 + rr*64 + lane + 32] = p1;
        }
        __syncwarp();

        #pragma unroll 4
        for (int kk = 0; kk < 64; kk++) {
            float v0 = Vs[kk*65 + lane];
            float v1 = Vs[kk*65 + lane + 32];
            #pragma unroll
            for (int rr = 0; rr < 8; rr++) {
                float p = Ps[w*512 + rr*64 + kk];
                a0[rr] += p * v0;
                a1[rr] += p * v1;
            }
        }
        __syncwarp();
        __syncthreads();
    }
    #pragma unroll
    for (int rr = 0; rr < 8; rr++) {
        int r = w*8 + rr;
        float inv = 1.0f / lrow[rr];
        size_t o = (size_t)(b*NS + r)*DMODEL + h*HD;
        float v0 = a0[rr] * inv, v1 = a1[rr] * inv;
        bf16 hh, ll;
        split2(v0, hh, ll); Oh[o + lane]      = hh; Ol[o + lane]      = ll;
        split2(v1, hh, ll); Oh[o + lane + 32] = hh; Ol[o + lane + 32] = ll;
    }
}

// ================= final row softmax over VOCAB (in-place) =================
__global__ void softmax_kernel(float* __restrict__ out) {
    __shared__ float buf[NVOCAB];
    __shared__ float red[8];
    const int tid = threadIdx.x, w = tid >> 5, lane = tid & 31;
    float* p = out + (size_t)blockIdx.x * NVOCAB;

    float mx = -1e30f;
    for (int i = tid; i < NVOCAB; i += 256) { float v = p[i]; buf[i] = v; mx = fmaxf(mx, v); }
    #pragma unroll
    for (int o = 16; o > 0; o >>= 1) mx = fmaxf(mx, __shfl_xor_sync(0xffffffffu, mx, o));
    if (lane == 0) red[w] = mx;
    __syncthreads();
    mx = red[0];
    #pragma unroll
    for (int i = 1; i < 8; i++) mx = fmaxf(mx, red[i]);
    __syncthreads();

    float sum = 0.f;
    for (int i = tid; i < NVOCAB; i += 256) { float e = __expf(buf[i] - mx); buf[i] = e; sum += e; }
    #pragma unroll
    for (int o = 16; o > 0; o >>= 1) sum += __shfl_xor_sync(0xffffffffu, sum, o);
    if (lane == 0) red[w] = sum;
    __syncthreads();
    sum = 0.f;
    #pragma unroll
    for (int i = 0; i < 8; i++) sum += red[i];
    float inv = 1.0f / sum;
    for (int i = tid; i < NVOCAB; i += 256) p[i] = buf[i] * inv;
}

// ================= host launcher =================
extern "C" void kernel_launch(void* const* d_in, const int* in_sizes, int n_in,
                              void* d_out, int out_size) {
    const int*   x   = (const int*)  d_in[0];
    const float* Kin = (const float*)d_in[1];
    const float* Vin = (const float*)d_in[2];
    const float* g   = (const float*)d_in[3];
    int i = 4;
    if (i < n_in && in_sizes[i] == 1) i++;
    const float* emb  = (const float*)d_in[i++];
    const float* Wq_s = (const float*)d_in[i++];
    const float* Wk_s = (const float*)d_in[i++];
    const float* Wv_s = (const float*)d_in[i++];
    const float* Wo_s = (const float*)d_in[i++];
    const float* Wq_c = (const float*)d_in[i++];
    const float* Wg_c = (const float*)d_in[i++];
    const float* Wk_c = (const float*)d_in[i++];
    const float* Wv_c = (const float*)d_in[i++];
    const float* Wo_c = (const float*)d_in[i++];
    const float* Wf   = (const float*)d_in[i++];
    const float* bf   = (const float*)d_in[i++];

    bf16 *actH, *actL, *aoH, *aoL, *KinH, *KinL, *VinH, *VinL, *gH, *gL, *wTH, *wTL, *wfTH, *wfTL;
    float *q, *k, *v, *kc, *vc, *gq;
    cudaGetSymbolAddress((void**)&actH, g_actH);  cudaGetSymbolAddress((void**)&actL, g_actL);
    cudaGetSymbolAddress((void**)&aoH,  g_aoH);   cudaGetSymbolAddress((void**)&aoL,  g_aoL);
    cudaGetSymbolAddress((void**)&KinH, g_KinH);  cudaGetSymbolAddress((void**)&KinL, g_KinL);
    cudaGetSymbolAddress((void**)&VinH, g_VinH);  cudaGetSymbolAddress((void**)&VinL, g_VinL);
    cudaGetSymbolAddress((void**)&gH,   g_gH);    cudaGetSymbolAddress((void**)&gL,   g_gL);
    cudaGetSymbolAddress((void**)&wTH,  g_wTH);   cudaGetSymbolAddress((void**)&wTL,  g_wTL);
    cudaGetSymbolAddress((void**)&wfTH, g_wfTH);  cudaGetSymbolAddress((void**)&wfTL, g_wfTL);
    cudaGetSymbolAddress((void**)&q,  g_q);  cudaGetSymbolAddress((void**)&k, g_k);
    cudaGetSymbolAddress((void**)&v,  g_v);
    cudaGetSymbolAddress((void**)&kc, g_kc); cudaGetSymbolAddress((void**)&vc, g_vc);
    cudaGetSymbolAddress((void**)&gq, g_gq);

    // one-time stream/event setup (first call is the uncaptured correctness run)
    static cudaStream_t sAux = nullptr;
    static cudaEvent_t eFork = nullptr, eWf = nullptr, eGq = nullptr, eCross[LLAYERS];
    if (!sAux) {
        cudaStreamCreateWithFlags(&sAux, cudaStreamNonBlocking);
        cudaEventCreateWithFlags(&eFork, cudaEventDisableTiming);
        cudaEventCreateWithFlags(&eWf,   cudaEventDisableTiming);
        cudaEventCreateWithFlags(&eGq,   cudaEventDisableTiming);
        for (int l = 0; l < LLAYERS; l++)
            cudaEventCreateWithFlags(&eCross[l], cudaEventDisableTiming);
    }

    const int ATTN_SMEM = ATTN_SMEM_FLOATS * (int)sizeof(float);
    cudaFuncSetAttribute(attn_kernel<true>,  cudaFuncAttributeMaxDynamicSharedMemorySize, ATTN_SMEM);
    cudaFuncSetAttribute(attn_kernel<false>, cudaFuncAttributeMaxDynamicSharedMemorySize, ATTN_SMEM);
    cudaFuncSetAttribute(gemm_plain64s, cudaFuncAttributeMaxDynamicSharedMemorySize, SMEM64S);
    cudaFuncSetAttribute(gemm_qkv3,     cudaFuncAttributeMaxDynamicSharedMemorySize, SMEM64);
    cudaFuncSetAttribute(gemm_gq6,      cudaFuncAttributeMaxDynamicSharedMemorySize, SMEM64);
    cudaFuncSetAttribute(gemm_cross2,   cudaFuncAttributeMaxDynamicSharedMemorySize, SMEM128);
    cudaFuncSetAttribute(gemm_final128, cudaFuncAttributeMaxDynamicSharedMemorySize, SMEM128);

    // ---- main stream: weights + input splits (everything the fork needs) ----
    WPtrs wp;
    wp.p[0]=Wq_s; wp.p[1]=Wk_s; wp.p[2]=Wv_s; wp.p[3]=Wo_s; wp.p[4]=Wq_c;
    wp.p[5]=Wg_c; wp.p[6]=Wk_c; wp.p[7]=Wv_c; wp.p[8]=Wo_c;
    wconv_all_kernel<<<dim3(16, 16, 9*LLAYERS), dim3(32, 8)>>>(wp, wTH, wTL);
    split_kernel<<<((int)CSZ/4 + 255)/256, 256>>>(Kin, KinH, KinL, (int)CSZ);
    split_kernel<<<((int)CSZ/4 + 255)/256, 256>>>(Vin, VinH, VinL, (int)CSZ);
    split_kernel<<<(NB*DMODEL/4 + 255)/256, 256>>>(g, gH, gL, NB*DMODEL);

    // ---- fork aux stream: cross K/V projections, g-projection, Wf conversion ----
    cudaEventRecord(eFork, 0);
    cudaStreamWaitEvent(sAux, eFork, 0);
    gemm_gq6<<<dim3(8, 1, LLAYERS), 256, SMEM64, sAux>>>(gH, gL, wTH, wTL, gq);
    cudaEventRecord(eGq, sAux);
    for (int l = 0; l < LLAYERS; l++) {
        gemm_cross2<<<dim3(4, NCTOK/128, 2), 256, SMEM128, sAux>>>(
            KinH, KinL, VinH, VinL, wTH, wTL, l,
            kc + (size_t)l*CSZ, vc + (size_t)l*CSZ);
        cudaEventRecord(eCross[l], sAux);
    }
    wconv_kernel<<<dim3((NVOCAB + 31)/32, 16, 1), dim3(32, 8), 0, sAux>>>(
        Wf, wfTH, wfTL, DMODEL, NVOCAB);
    cudaEventRecord(eWf, sAux);

    // ---- main stream: embedding + layer loop ----
    embed_kernel<<<NTOK, 128>>>(x, emb, actH, actL);
    cudaStreamWaitEvent(0, eGq, 0);

    for (int l = 0; l < LLAYERS; l++) {
        gemm_qkv3<<<dim3(8, NTOK/128, 3), 256, SMEM64>>>(actH, actL, wTH, wTL, l, q, k, v);
        attn_kernel<true><<<NB*NH, 256, ATTN_SMEM>>>(q, k, v, aoH, aoL, NS, NS);
        gemm_plain64s<<<dim3(8, NTOK/64), 128, SMEM64S>>>(
            aoH, aoL, wTH + ((size_t)3*LLAYERS + l)*WSZ, wTL + ((size_t)3*LLAYERS + l)*WSZ,
            nullptr, actH, actL, NTOK, DMODEL, nullptr, nullptr);

        gemm_plain64s<<<dim3(8, NTOK/64), 128, SMEM64S>>>(
            actH, actL, wTH + ((size_t)4*LLAYERS + l)*WSZ, wTL + ((size_t)4*LLAYERS + l)*WSZ,
            q, nullptr, nullptr, NTOK, DMODEL, gq + (size_t)l*NB*DMODEL, nullptr);
        cudaStreamWaitEvent(0, eCross[l], 0);
        attn_kernel<false><<<NB*NH, 256, ATTN_SMEM>>>(
            q, kc + (size_t)l*CSZ, vc + (size_t)l*CSZ, aoH, aoL, NNR, NNR);
        gemm_plain64s<<<dim3(8, NTOK/64), 128, SMEM64S>>>(
            aoH, aoL, wTH + ((size_t)8*LLAYERS + l)*WSZ, wTL + ((size_t)8*LLAYERS + l)*WSZ,
            nullptr, actH, actL, NTOK, DMODEL, nullptr, nullptr);
    }

    // ---- join: final projection needs Wf conversion from aux ----
    cudaStreamWaitEvent(0, eWf, 0);
    gemm_final128<<<dim3((NVOCAB + 127)/128, NTOK/128), 256, SMEM128>>>(
        actH, actL, wfTH, wfTL, (float*)d_out, NTOK, NVOCAB, bf);
    softmax_kernel<<<NTOK, 256>>>((float*)d_out);
}

// round 12
// speedup vs baseline: 1.0718x; 1.0718x over previous
#include <cuda_runtime.h>
#include <cuda_bf16.h>
#include <math.h>
#include <stdint.h>

typedef __nv_bfloat16 bf16;

#define LLAYERS 6
#define DMODEL  512
#define NH      8
#define HD      64
#define NVOCAB  10000
#define NB      32
#define NS      64
#define NNR     196
#define NTOK    (NB*NS)     // 2048
#define NCTOK   (NB*NNR)    // 6272
#define WSZ     ((size_t)DMODEL*DMODEL)
#define CSZ     ((size_t)NCTOK*DMODEL)

// ================= scratch =================
__device__ bf16  g_actH[NTOK*DMODEL], g_actL[NTOK*DMODEL];
__device__ float g_q[NTOK*DMODEL], g_k[NTOK*DMODEL], g_v[NTOK*DMODEL];
__device__ bf16  g_aoH[NTOK*DMODEL], g_aoL[NTOK*DMODEL];
__device__ float g_kc[LLAYERS][CSZ], g_vc[LLAYERS][CSZ];
__device__ float g_gq[LLAYERS][NB*DMODEL];
__device__ bf16  g_KinH[CSZ], g_KinL[CSZ], g_VinH[CSZ], g_VinL[CSZ];
__device__ bf16  g_gH[NB*DMODEL], g_gL[NB*DMODEL];
__device__ bf16  g_wTH[9*LLAYERS*WSZ], g_wTL[9*LLAYERS*WSZ];   // [N,K] transposed
__device__ bf16  g_wfTH[(size_t)NVOCAB*DMODEL], g_wfTL[(size_t)NVOCAB*DMODEL];
__device__ bf16  g_WosH[LLAYERS*WSZ], g_WosL[LLAYERS*WSZ];     // raw Wo_s row-major split
__device__ bf16  g_wscH[LLAYERS*WSZ], g_wscL[LLAYERS*WSZ];     // (Wo_s@Wq_c)^T hi/lo

// ================= helpers =================
__device__ __forceinline__ uint32_t smem_to_u32(const void* p) {
    uint32_t a;
    asm("{ .reg .u64 t; cvta.to.shared.u64 t, %1; cvt.u32.u64 %0, t; }" : "=r"(a) : "l"(p));
    return a;
}
__device__ __forceinline__ void cp16(uint32_t dst, const void* src, bool p) {
    int sz = p ? 16 : 0;
    asm volatile("cp.async.cg.shared.global [%0], [%1], 16, %2;" :: "r"(dst), "l"(src), "r"(sz) : "memory");
}
#define CP_COMMIT() asm volatile("cp.async.commit_group;" ::: "memory")
#define CP_WAIT0()  asm volatile("cp.async.wait_group 0;" ::: "memory")
#define CP_WAIT1()  asm volatile("cp.async.wait_group 1;" ::: "memory")

__device__ __forceinline__ void ldm4(uint32_t addr, uint32_t* r) {
    asm volatile("ldmatrix.sync.aligned.m8n8.x4.shared.b16 {%0,%1,%2,%3}, [%4];"
        : "=r"(r[0]), "=r"(r[1]), "=r"(r[2]), "=r"(r[3]) : "r"(addr));
}
__device__ __forceinline__ void mma16816(float* c, const uint32_t* a, uint32_t b0, uint32_t b1) {
    asm volatile("mma.sync.aligned.m16n8k16.row.col.f32.bf16.bf16.f32 "
        "{%0,%1,%2,%3}, {%4,%5,%6,%7}, {%8,%9}, {%0,%1,%2,%3};"
        : "+f"(c[0]), "+f"(c[1]), "+f"(c[2]), "+f"(c[3])
        : "r"(a[0]), "r"(a[1]), "r"(a[2]), "r"(a[3]), "r"(b0), "r"(b1));
}
__device__ __forceinline__ void split2(float v, bf16& h, bf16& l) {
    h = __float2bfloat16(v);
    l = __float2bfloat16(v - __bfloat162float(h));
}

// ================= conversion kernels =================
union BPack { bf16 b[4]; uint2 u; };

__global__ void split_kernel(const float* __restrict__ src, bf16* __restrict__ h,
                             bf16* __restrict__ l, int n) {
    int i = (blockIdx.x * blockDim.x + threadIdx.x) * 4;
    if (i < n) {
        float4 v = *(const float4*)(src + i);
        BPack ph, pl;
        split2(v.x, ph.b[0], pl.b[0]);
        split2(v.y, ph.b[1], pl.b[1]);
        split2(v.z, ph.b[2], pl.b[2]);
        split2(v.w, ph.b[3], pl.b[3]);
        *(uint2*)(h + i) = ph.u;
        *(uint2*)(l + i) = pl.u;
    }
}

struct WPtrs { const float* p[9]; };

__global__ void wconv_all_kernel(WPtrs wp, bf16* __restrict__ Th, bf16* __restrict__ Tl) {
    __shared__ float t[32][33];
    const int z = blockIdx.z, m = z / LLAYERS, l = z % LLAYERS;
    const float* Wz = wp.p[m] + (size_t)l * WSZ;
    bf16* Thz = Th + ((size_t)m*LLAYERS + l) * WSZ;
    bf16* Tlz = Tl + ((size_t)m*LLAYERS + l) * WSZ;
    int n0 = blockIdx.x * 32, k0 = blockIdx.y * 32;
    int tx = threadIdx.x, ty = threadIdx.y;
    for (int r = ty; r < 32; r += 8) {
        t[r][tx] = Wz[(size_t)(k0 + r) * DMODEL + n0 + tx];
    }
    __syncthreads();
    for (int r = ty; r < 32; r += 8) {
        bf16 hh, ll; split2(t[tx][r], hh, ll);
        Thz[(size_t)(n0 + r) * DMODEL + k0 + tx] = hh;
        Tlz[(size_t)(n0 + r) * DMODEL + k0 + tx] = ll;
    }
}

__global__ void wconv_kernel(const float* __restrict__ W, bf16* __restrict__ Th,
                             bf16* __restrict__ Tl, int Kdim, int Ndim) {
    __shared__ float t[32][33];
    int n0 = blockIdx.x * 32, k0 = blockIdx.y * 32;
    int tx = threadIdx.x, ty = threadIdx.y;
    for (int r = ty; r < 32; r += 8) {
        int n = n0 + tx;
        t[r][tx] = (n < Ndim) ? W[(size_t)(k0 + r) * Ndim + n] : 0.f;
    }
    __syncthreads();
    for (int r = ty; r < 32; r += 8) {
        int n = n0 + r;
        if (n < Ndim) {
            bf16 hh, ll; split2(t[tx][r], hh, ll);
            Th[(size_t)n * Kdim + k0 + tx] = hh;
            Tl[(size_t)n * Kdim + k0 + tx] = ll;
        }
    }
}

// ================= embedding + positional encoding =================
__global__ void embed_kernel(const int* __restrict__ x, const float* __restrict__ emb,
                             bf16* __restrict__ outH, bf16* __restrict__ outL) {
    int t = blockIdx.x;
    int s = t % NS;
    int tok = x[t];
    for (int d = threadIdx.x; d < DMODEL; d += blockDim.x) {
        int j = d >> 1;
        float ang = (float)s * powf(10000.0f, -(2.0f*(float)j)/(float)DMODEL);
        float pe = (d & 1) ? cosf(ang) : sinf(ang);
        float v = emb[tok*DMODEL + d] + pe;
        bf16 hh, ll; split2(v, hh, ll);
        outH[t*DMODEL + d] = hh; outL[t*DMODEL + d] = ll;
    }
}

// ================= split-bf16 HMMA GEMM (K-chunk 32, templated stages) ========
#define NCHUNK   16
#define STRIDE   40
#define TILE_A   (128*STRIDE*2)
template<int NT, int STAGES> struct TileCfg {
    static const int TB  = NT*STRIDE*2;
    static const int BUF = 2*TILE_A + 2*TB;
    static const int SMEM = STAGES*BUF;
    static const int NP  = NT/32;
};

template<int NT, int STAGES>
__device__ __forceinline__ void load_tiles(
    const bf16* __restrict__ Ah, const bf16* __restrict__ Al,
    const bf16* __restrict__ Bh, const bf16* __restrict__ Bl,
    int M, int N, int m0, int n0, int ch, uint32_t sbuf, int tid)
{
    typedef TileCfg<NT, STAGES> TC;
    {
        const int row = tid >> 1;
        const int qd  = (tid & 1) * 2;
        const uint32_t sof = sbuf + (uint32_t)(row*STRIDE + qd*8) * 2;
        bool ok = (m0 + row) < M;
        const bf16* pa = Ah + (size_t)(m0 + row) * 512 + ch*32 + qd*8;
        const bf16* pl = Al + (size_t)(m0 + row) * 512 + ch*32 + qd*8;
        cp16(sof,                pa,     ok);
        cp16(sof + 16,           pa + 8, ok);
        cp16(sof + TILE_A,       pl,     ok);
        cp16(sof + TILE_A + 16,  pl + 8, ok);
    }
    if (NT == 128) {
        const int row = tid >> 1;
        const int qd  = (tid & 1) * 2;
        const uint32_t sof = sbuf + 2*TILE_A + (uint32_t)(row*STRIDE + qd*8) * 2;
        bool ok = (n0 + row) < N;
        const bf16* pb = Bh + (size_t)(n0 + row) * 512 + ch*32 + qd*8;
        const bf16* pl = Bl + (size_t)(n0 + row) * 512 + ch*32 + qd*8;
        cp16(sof,            pb,     ok);
        cp16(sof + 16,       pb + 8, ok);
        cp16(sof + TC::TB,       pl,     ok);
        cp16(sof + TC::TB + 16,  pl + 8, ok);
    } else {
        const int row = tid >> 2;
        const int qd  = tid & 3;
        const uint32_t sof = sbuf + 2*TILE_A + (uint32_t)(row*STRIDE + qd*8) * 2;
        bool ok = (n0 + row) < N;
        cp16(sof,            Bh + (size_t)(n0 + row) * 512 + ch*32 + qd*8, ok);
        cp16(sof + TC::TB,   Bl + (size_t)(n0 + row) * 512 + ch*32 + qd*8, ok);
    }
}

template<int NT, int STAGES>
__device__ void gemm_core(const bf16* __restrict__ Ah, const bf16* __restrict__ Al,
                          const bf16* __restrict__ Bh, const bf16* __restrict__ Bl,
                          float* __restrict__ C, bf16* __restrict__ Ch, bf16* __restrict__ Cl,
                          int M, int N,
                          const float* __restrict__ rowBias, const float* __restrict__ colBias)
{
    typedef TileCfg<NT, STAGES> TC;
    extern __shared__ char smem[];
    const uint32_t sb = smem_to_u32(smem);
    const int tid = threadIdx.x, wid = tid >> 5, lane = tid & 31;
    const int wm = wid & 3, wn = wid >> 2;
    const int m0 = blockIdx.y * 128, n0 = blockIdx.x * NT;
    const int NP = TC::NP;
    const int BUF = TC::BUF;
    const int TB = TC::TB;

    float acc[2][2*TC::NP][4];
    #pragma unroll
    for (int i = 0; i < 2; i++)
        #pragma unroll
        for (int j = 0; j < 2*NP; j++)
            #pragma unroll
            for (int e = 0; e < 4; e++) acc[i][j][e] = 0.f;

    #pragma unroll
    for (int s = 0; s < STAGES-1; s++) {
        load_tiles<NT, STAGES>(Ah, Al, Bh, Bl, M, N, m0, n0, s, sb + s*BUF, tid);
        CP_COMMIT();
    }

    int cur = 0;
    const int aRow = (lane & 15);
    const int aCol = (lane >> 4) << 3;
    const int bRow = (lane & 7) + (((lane >> 4) & 1) << 3);
    const int bCol = ((lane >> 3) & 1) << 3;

    #pragma unroll 1
    for (int ch = 0; ch < NCHUNK; ch++) {
        if (STAGES == 3 && ch < NCHUNK-1) { CP_WAIT1(); } else { CP_WAIT0(); }
        __syncthreads();
        if (ch + STAGES - 1 < NCHUNK) {
            int nb = cur + STAGES - 1; if (nb >= STAGES) nb -= STAGES;
            load_tiles<NT, STAGES>(Ah, Al, Bh, Bl, M, N, m0, n0, ch + STAGES - 1, sb + nb*BUF, tid);
            CP_COMMIT();
        }
        const uint32_t sAh = sb + cur*BUF;
        const uint32_t sAl = sAh + TILE_A;
        const uint32_t sBh = sAh + 2*TILE_A;
        const uint32_t sBl = sBh + TB;

        #pragma unroll
        for (int k16 = 0; k16 < 32; k16 += 16) {
            uint32_t ah[8], al[8];
            uint32_t bh[TC::NP][4], bl[TC::NP][4];
            {
                uint32_t a0 = (uint32_t)((wm*32 + aRow)*STRIDE + k16 + aCol) * 2;
                uint32_t a1 = (uint32_t)((wm*32 + 16 + aRow)*STRIDE + k16 + aCol) * 2;
                ldm4(sAh + a0, ah);  ldm4(sAh + a1, ah + 4);
                ldm4(sAl + a0, al);  ldm4(sAl + a1, al + 4);
            }
            #pragma unroll
            for (int np = 0; np < NP; np++) {
                const int nb2 = wn*(NT/2) + np*16;
                const uint32_t boff = (uint32_t)((nb2 + bRow)*STRIDE + k16 + bCol) * 2;
                ldm4(sBh + boff, bh[np]);
                ldm4(sBl + boff, bl[np]);
            }
            #pragma unroll
            for (int np = 0; np < NP; np++)
                #pragma unroll
                for (int mi = 0; mi < 2; mi++) {
                    mma16816(acc[mi][np*2],     ah + 4*mi, bh[np][0], bh[np][1]);
                    mma16816(acc[mi][np*2 + 1], ah + 4*mi, bh[np][2], bh[np][3]);
                }
            #pragma unroll
            for (int np = 0; np < NP; np++)
                #pragma unroll
                for (int mi = 0; mi < 2; mi++) {
                    mma16816(acc[mi][np*2],     ah + 4*mi, bl[np][0], bl[np][1]);
                    mma16816(acc[mi][np*2 + 1], ah + 4*mi, bl[np][2], bl[np][3]);
                }
            #pragma unroll
            for (int np = 0; np < NP; np++)
                #pragma unroll
                for (int mi = 0; mi < 2; mi++) {
                    mma16816(acc[mi][np*2],     al + 4*mi, bh[np][0], bh[np][1]);
                    mma16816(acc[mi][np*2 + 1], al + 4*mi, bh[np][2], bh[np][3]);
                }
        }
        cur++; if (cur == STAGES) cur = 0;
    }

    // epilogue
    const int r0 = m0 + wm*32 + (lane >> 2);
    const int c0 = n0 + wn*(NT/2) + (lane & 3) * 2;
    #pragma unroll
    for (int mi = 0; mi < 2; mi++) {
        #pragma unroll
        for (int na = 0; na < 2*NP; na++) {
            const int col = c0 + (na >> 1)*16 + (na & 1)*8;
            #pragma unroll
            for (int e = 0; e < 4; e++) {
                const int r = r0 + mi*16 + ((e >> 1) << 3);
                const int c = col + (e & 1);
                if (r >= M || c >= N) continue;
                float v = acc[mi][na][e];
                if (rowBias) v += rowBias[(size_t)(r >> 6) * N + c];
                if (colBias) v += colBias[c];
                if (C) C[(size_t)r * N + c] = v;
                if (Ch) {
                    bf16 hh, ll; split2(v, hh, ll);
                    Ch[(size_t)r * N + c] = hh;
                    Cl[(size_t)r * N + c] = ll;
                }
            }
        }
    }
}

#define SMEM64  (TileCfg<64,3>::SMEM)     // 92160 B
#define SMEM128 (TileCfg<128,2>::SMEM)    // 81920 B

__global__ void __launch_bounds__(256, 2) gemm_plain64(
    const bf16* Ah, const bf16* Al, const bf16* Bh, const bf16* Bl,
    float* C, bf16* Ch, bf16* Cl, int M, int N,
    const float* rowBias, const float* colBias) {
    gemm_core<64,3>(Ah, Al, Bh, Bl, C, Ch, Cl, M, N, rowBias, colBias);
}

__global__ void __launch_bounds__(256, 2) gemm_final128(
    const bf16* Ah, const bf16* Al, const bf16* Bh, const bf16* Bl,
    float* C, int M, int N, const float* colBias) {
    gemm_core<128,2>(Ah, Al, Bh, Bl, C, nullptr, nullptr, M, N, nullptr, colBias);
}

__global__ void __launch_bounds__(256, 2) gemm_qkv3(
    const bf16* Ah, const bf16* Al, const bf16* wTH, const bf16* wTL, int l,
    float* q, float* k, float* v) {
    const int z = blockIdx.z;
    const size_t off = ((size_t)z*LLAYERS + l) * WSZ;
    float* C = (z == 0) ? q : (z == 1) ? k : v;
    gemm_core<64,3>(Ah, Al, wTH + off, wTL + off, C, nullptr, nullptr, NTOK, DMODEL, nullptr, nullptr);
}

// combined weight precompute: WscT[l] = Wq_c[l]^T (.) Wo_s[l]  (C[n,m] = sum_k A[n,k]B[m,k])
__global__ void __launch_bounds__(256, 2) gemm_wsc6(
    const bf16* wTH, const bf16* wTL, const bf16* WosH, const bf16* WosL,
    bf16* wscH, bf16* wscL) {
    const int l = blockIdx.z;
    const size_t aoff = ((size_t)4*LLAYERS + l) * WSZ;   // Wq_c transposed split
    const size_t boff = (size_t)l * WSZ;
    gemm_core<64,3>(wTH + aoff, wTL + aoff, WosH + boff, WosL + boff,
                    nullptr, wscH + boff, wscL + boff, DMODEL, DMODEL, nullptr, nullptr);
}

__global__ void __launch_bounds__(256, 2) gemm_cross2(
    const bf16* KinH, const bf16* KinL, const bf16* VinH, const bf16* VinL,
    const bf16* wTH, const bf16* wTL, int l, float* kc, float* vc) {
    const int kv = blockIdx.z;
    const size_t woff = ((size_t)(6 + kv)*LLAYERS + l) * WSZ;
    gemm_core<128,2>(kv ? VinH : KinH, kv ? VinL : KinL, wTH + woff, wTL + woff,
                     kv ? vc : kc, nullptr, nullptr, NCTOK, DMODEL, nullptr, nullptr);
}

__global__ void __launch_bounds__(256, 2) gemm_gq6(
    const bf16* gH, const bf16* gL, const bf16* wTH, const bf16* wTL, float* gq) {
    const int l = blockIdx.z;
    const size_t woff = ((size_t)5*LLAYERS + l) * WSZ;
    gemm_core<64,3>(gH, gL, wTH + woff, wTL + woff,
                    gq + (size_t)l*NB*DMODEL, nullptr, nullptr, NB, DMODEL, nullptr, nullptr);
}

// ================= fused attention (fp32, register-blocked), writes hi/lo ======
#define ATTN_SMEM_FLOATS (3*64*65 + 8*512)
template<bool CAUSAL>
__global__ void attn_kernel(const float* __restrict__ Q, const float* __restrict__ Kb,
                            const float* __restrict__ Vb,
                            bf16* __restrict__ Oh, bf16* __restrict__ Ol,
                            int skeys, int kvTokens) {
    extern __shared__ float sm[];
    float* Qs = sm;
    float* Ks = sm + 64*65;
    float* Vs = sm + 2*64*65;
    float* Ps = sm + 3*64*65;

    const int b = blockIdx.x / NH, h = blockIdx.x % NH;
    const int tid = threadIdx.x, w = tid >> 5, lane = tid & 31;

    for (int i = tid; i < 64*64; i += 256) {
        int r = i >> 6, c = i & 63;
        Qs[r*65 + c] = Q[(size_t)(b*NS + r)*DMODEL + h*HD + c];
    }
    float mrow[8], lrow[8], a0[8], a1[8];
    #pragma unroll
    for (int i = 0; i < 8; i++) { mrow[i] = -1e30f; lrow[i] = 0.f; a0[i] = 0.f; a1[i] = 0.f; }
    __syncthreads();

    const int nch = (skeys + 63) >> 6;
    for (int ch = 0; ch < nch; ch++) {
        const int kb = ch * 64;
        const int cnt = min(64, skeys - kb);
        for (int i = tid; i < 64*64; i += 256) {
            int r = i >> 6, c = i & 63;
            float kv = 0.f, vv = 0.f;
            if (r < cnt) {
                size_t off = (size_t)(b*kvTokens + kb + r)*DMODEL + h*HD + c;
                kv = Kb[off]; vv = Vb[off];
            }
            Ks[r*65 + c] = kv; Vs[r*65 + c] = vv;
        }
        __syncthreads();

        float d0[8], d1[8];
        #pragma unroll
        for (int i = 0; i < 8; i++) { d0[i] = 0.f; d1[i] = 0.f; }
        #pragma unroll 4
        for (int d = 0; d < 64; d++) {
            float k0 = Ks[lane*65 + d];
            float k1 = Ks[(lane+32)*65 + d];
            #pragma unroll
            for (int rr = 0; rr < 8; rr++) {
                float qv = Qs[(w*8 + rr)*65 + d];
                d0[rr] += qv * k0;
                d1[rr] += qv * k1;
            }
        }

        #pragma unroll
        for (int rr = 0; rr < 8; rr++) {
            const int r = w*8 + rr;
            float s0 = d0[rr] * 0.125f, s1 = d1[rr] * 0.125f;
            bool v0 = (lane      < cnt) && (!CAUSAL || (kb + lane)      <= r);
            bool v1 = (lane + 32 < cnt) && (!CAUSAL || (kb + lane + 32) <= r);
            if (!v0) s0 = -1e30f;
            if (!v1) s1 = -1e30f;
            float cm = fmaxf(s0, s1);
            #pragma unroll
            for (int o = 16; o > 0; o >>= 1) cm = fmaxf(cm, __shfl_xor_sync(0xffffffffu, cm, o));
            float nm = fmaxf(mrow[rr], cm);
            float corr = __expf(mrow[rr] - nm);
            float p0 = v0 ? __expf(s0 - nm) : 0.f;
            float p1 = v1 ? __expf(s1 - nm) : 0.f;
            float ps = p0 + p1;
            #pragma unroll
            for (int o = 16; o > 0; o >>= 1) ps += __shfl_xor_sync(0xffffffffu, ps, o);
            lrow[rr] = lrow[rr]*corr + ps;
            mrow[rr] = nm;
            a0[rr] *= corr; a1[rr] *= corr;
            Ps[w*512 + rr*64 + lane]      = p0;
            Ps[w*512 + rr*64 + lane + 32] = p1;
        }
        __syncwarp();

        #pragma unroll 4
        for (int kk = 0; kk < 64; kk++) {
            float v0 = Vs[kk*65 + lane];
            float v1 = Vs[kk*65 + lane + 32];
            #pragma unroll
            for (int rr = 0; rr < 8; rr++) {
                float p = Ps[w*512 + rr*64 + kk];
                a0[rr] += p * v0;
                a1[rr] += p * v1;
            }
        }
        __syncwarp();
        __syncthreads();
    }
    #pragma unroll
    for (int rr = 0; rr < 8; rr++) {
        int r = w*8 + rr;
        float inv = 1.0f / lrow[rr];
        size_t o = (size_t)(b*NS + r)*DMODEL + h*HD;
        float v0 = a0[rr] * inv, v1 = a1[rr] * inv;
        bf16 hh, ll;
        split2(v0, hh, ll); Oh[o + lane]      = hh; Ol[o + lane]      = ll;
        split2(v1, hh, ll); Oh[o + lane + 32] = hh; Ol[o + lane + 32] = ll;
    }
}

// ================= final row softmax over VOCAB (in-place) =================
__global__ void softmax_kernel(float* __restrict__ out) {
    __shared__ float buf[NVOCAB];
    __shared__ float red[8];
    const int tid = threadIdx.x, w = tid >> 5, lane = tid & 31;
    float* p = out + (size_t)blockIdx.x * NVOCAB;

    float mx = -1e30f;
    for (int i = tid; i < NVOCAB; i += 256) { float v = p[i]; buf[i] = v; mx = fmaxf(mx, v); }
    #pragma unroll
    for (int o = 16; o > 0; o >>= 1) mx = fmaxf(mx, __shfl_xor_sync(0xffffffffu, mx, o));
    if (lane == 0) red[w] = mx;
    __syncthreads();
    mx = red[0];
    #pragma unroll
    for (int i = 1; i < 8; i++) mx = fmaxf(mx, red[i]);
    __syncthreads();

    float sum = 0.f;
    for (int i = tid; i < NVOCAB; i += 256) { float e = __expf(buf[i] - mx); buf[i] = e; sum += e; }
    #pragma unroll
    for (int o = 16; o > 0; o >>= 1) sum += __shfl_xor_sync(0xffffffffu, sum, o);
    if (lane == 0) red[w] = sum;
    __syncthreads();
    sum = 0.f;
    #pragma unroll
    for (int i = 0; i < 8; i++) sum += red[i];
    float inv = 1.0f / sum;
    for (int i = tid; i < NVOCAB; i += 256) p[i] = buf[i] * inv;
}

// ================= host launcher =================
extern "C" void kernel_launch(void* const* d_in, const int* in_sizes, int n_in,
                              void* d_out, int out_size) {
    const int*   x   = (const int*)  d_in[0];
    const float* Kin = (const float*)d_in[1];
    const float* Vin = (const float*)d_in[2];
    const float* g   = (const float*)d_in[3];
    int i = 4;
    if (i < n_in && in_sizes[i] == 1) i++;
    const float* emb  = (const float*)d_in[i++];
    const float* Wq_s = (const float*)d_in[i++];
    const float* Wk_s = (const float*)d_in[i++];
    const float* Wv_s = (const float*)d_in[i++];
    const float* Wo_s = (const float*)d_in[i++];
    const float* Wq_c = (const float*)d_in[i++];
    const float* Wg_c = (const float*)d_in[i++];
    const float* Wk_c = (const float*)d_in[i++];
    const float* Wv_c = (const float*)d_in[i++];
    const float* Wo_c = (const float*)d_in[i++];
    const float* Wf   = (const float*)d_in[i++];
    const float* bf   = (const float*)d_in[i++];

    bf16 *actH, *actL, *aoH, *aoL, *KinH, *KinL, *VinH, *VinL, *gH, *gL;
    bf16 *wTH, *wTL, *wfTH, *wfTL, *WosH, *WosL, *wscH, *wscL;
    float *q, *k, *v, *kc, *vc, *gq;
    cudaGetSymbolAddress((void**)&actH, g_actH);  cudaGetSymbolAddress((void**)&actL, g_actL);
    cudaGetSymbolAddress((void**)&aoH,  g_aoH);   cudaGetSymbolAddress((void**)&aoL,  g_aoL);
    cudaGetSymbolAddress((void**)&KinH, g_KinH);  cudaGetSymbolAddress((void**)&KinL, g_KinL);
    cudaGetSymbolAddress((void**)&VinH, g_VinH);  cudaGetSymbolAddress((void**)&VinL, g_VinL);
    cudaGetSymbolAddress((void**)&gH,   g_gH);    cudaGetSymbolAddress((void**)&gL,   g_gL);
    cudaGetSymbolAddress((void**)&wTH,  g_wTH);   cudaGetSymbolAddress((void**)&wTL,  g_wTL);
    cudaGetSymbolAddress((void**)&wfTH, g_wfTH);  cudaGetSymbolAddress((void**)&wfTL, g_wfTL);
    cudaGetSymbolAddress((void**)&WosH, g_WosH);  cudaGetSymbolAddress((void**)&WosL, g_WosL);
    cudaGetSymbolAddress((void**)&wscH, g_wscH);  cudaGetSymbolAddress((void**)&wscL, g_wscL);
    cudaGetSymbolAddress((void**)&q,  g_q);  cudaGetSymbolAddress((void**)&k, g_k);
    cudaGetSymbolAddress((void**)&v,  g_v);
    cudaGetSymbolAddress((void**)&kc, g_kc); cudaGetSymbolAddress((void**)&vc, g_vc);
    cudaGetSymbolAddress((void**)&gq, g_gq);

    static cudaStream_t sAux = nullptr;
    static cudaEvent_t eFork = nullptr, eWf = nullptr, ePre = nullptr, eCross[LLAYERS];
    if (!sAux) {
        cudaStreamCreateWithFlags(&sAux, cudaStreamNonBlocking);
        cudaEventCreateWithFlags(&eFork, cudaEventDisableTiming);
        cudaEventCreateWithFlags(&eWf,   cudaEventDisableTiming);
        cudaEventCreateWithFlags(&ePre,  cudaEventDisableTiming);
        for (int l = 0; l < LLAYERS; l++)
            cudaEventCreateWithFlags(&eCross[l], cudaEventDisableTiming);
    }

    const int ATTN_SMEM = ATTN_SMEM_FLOATS * (int)sizeof(float);
    cudaFuncSetAttribute(attn_kernel<true>,  cudaFuncAttributeMaxDynamicSharedMemorySize, ATTN_SMEM);
    cudaFuncSetAttribute(attn_kernel<false>, cudaFuncAttributeMaxDynamicSharedMemorySize, ATTN_SMEM);
    cudaFuncSetAttribute(gemm_plain64,  cudaFuncAttributeMaxDynamicSharedMemorySize, SMEM64);
    cudaFuncSetAttribute(gemm_qkv3,     cudaFuncAttributeMaxDynamicSharedMemorySize, SMEM64);
    cudaFuncSetAttribute(gemm_gq6,      cudaFuncAttributeMaxDynamicSharedMemorySize, SMEM64);
    cudaFuncSetAttribute(gemm_wsc6,     cudaFuncAttributeMaxDynamicSharedMemorySize, SMEM64);
    cudaFuncSetAttribute(gemm_cross2,   cudaFuncAttributeMaxDynamicSharedMemorySize, SMEM128);
    cudaFuncSetAttribute(gemm_final128, cudaFuncAttributeMaxDynamicSharedMemorySize, SMEM128);

    // ---- main stream: weight conversions + input splits ----
    WPtrs wp;
    wp.p[0]=Wq_s; wp.p[1]=Wk_s; wp.p[2]=Wv_s; wp.p[3]=Wo_s; wp.p[4]=Wq_c;
    wp.p[5]=Wg_c; wp.p[6]=Wk_c; wp.p[7]=Wv_c; wp.p[8]=Wo_c;
    wconv_all_kernel<<<dim3(16, 16, 9*LLAYERS), dim3(32, 8)>>>(wp, wTH, wTL);
    split_kernel<<<((int)(LLAYERS*WSZ)/4 + 255)/256, 256>>>(Wo_s, WosH, WosL, (int)(LLAYERS*WSZ));
    split_kernel<<<((int)CSZ/4 + 255)/256, 256>>>(Kin, KinH, KinL, (int)CSZ);
    split_kernel<<<((int)CSZ/4 + 255)/256, 256>>>(Vin, VinH, VinL, (int)CSZ);
    split_kernel<<<(NB*DMODEL/4 + 255)/256, 256>>>(g, gH, gL, NB*DMODEL);

    // ---- fork aux stream ----
    cudaEventRecord(eFork, 0);
    cudaStreamWaitEvent(sAux, eFork, 0);
    gemm_wsc6<<<dim3(8, 4, LLAYERS), 256, SMEM64, sAux>>>(wTH, wTL, WosH, WosL, wscH, wscL);
    gemm_gq6 <<<dim3(8, 1, LLAYERS), 256, SMEM64, sAux>>>(gH, gL, wTH, wTL, gq);
    cudaEventRecord(ePre, sAux);
    for (int l = 0; l < LLAYERS; l++) {
        gemm_cross2<<<dim3(4, NCTOK/128, 2), 256, SMEM128, sAux>>>(
            KinH, KinL, VinH, VinL, wTH, wTL, l,
            kc + (size_t)l*CSZ, vc + (size_t)l*CSZ);
        cudaEventRecord(eCross[l], sAux);
    }
    wconv_kernel<<<dim3((NVOCAB + 31)/32, 16, 1), dim3(32, 8), 0, sAux>>>(
        Wf, wfTH, wfTL, DMODEL, NVOCAB);
    cudaEventRecord(eWf, sAux);

    // ---- main stream: embedding + layer loop ----
    embed_kernel<<<NTOK, 128>>>(x, emb, actH, actL);
    cudaStreamWaitEvent(0, ePre, 0);   // gq + Wsc ready before layer 0 fused GEMM

    for (int l = 0; l < LLAYERS; l++) {
        gemm_qkv3<<<dim3(8, NTOK/128, 3), 256, SMEM64>>>(actH, actL, wTH, wTL, l, q, k, v);
        attn_kernel<true><<<NB*NH, 256, ATTN_SMEM>>>(q, k, v, aoH, aoL, NS, NS);
        // fused (Wo_s @ Wq_c) projection: q = ao @ Wsc + gq
        gemm_plain64<<<dim3(8, NTOK/128), 256, SMEM64>>>(
            aoH, aoL, wscH + (size_t)l*WSZ, wscL + (size_t)l*WSZ,
            q, nullptr, nullptr, NTOK, DMODEL, gq + (size_t)l*NB*DMODEL, nullptr);
        cudaStreamWaitEvent(0, eCross[l], 0);
        attn_kernel<false><<<NB*NH, 256, ATTN_SMEM>>>(
            q, kc + (size_t)l*CSZ, vc + (size_t)l*CSZ, aoH, aoL, NNR, NNR);
        gemm_plain64<<<dim3(8, NTOK/128), 256, SMEM64>>>(
            aoH, aoL, wTH + ((size_t)8*LLAYERS + l)*WSZ, wTL + ((size_t)8*LLAYERS + l)*WSZ,
            nullptr, actH, actL, NTOK, DMODEL, nullptr, nullptr);
    }

    // ---- join: final projection needs Wf conversion from aux ----
    cudaStreamWaitEvent(0, eWf, 0);
    gemm_final128<<<dim3((NVOCAB + 127)/128, NTOK/128), 256, SMEM128>>>(
        actH, actL, wfTH, wfTL, (float*)d_out, NTOK, NVOCAB, bf);
    softmax_kernel<<<NTOK, 256>>>((float*)d_out);
}

// round 14
// speedup vs baseline: 1.0926x; 1.0194x over previous
#include <cuda_runtime.h>
#include <cuda_bf16.h>
#include <math.h>
#include <stdint.h>

typedef __nv_bfloat16 bf16;

#define LLAYERS 6
#define DMODEL  512
#define NH      8
#define HD      64
#define NVOCAB  10000
#define NB      32
#define NS      64
#define NNR     196
#define NTOK    (NB*NS)     // 2048
#define NCTOK   (NB*NNR)    // 6272
#define WSZ     ((size_t)DMODEL*DMODEL)
#define CSZ     ((size_t)NCTOK*DMODEL)

// ================= scratch =================
__device__ bf16  g_actH[NTOK*DMODEL], g_actL[NTOK*DMODEL];
__device__ float g_q[NTOK*DMODEL], g_k[NTOK*DMODEL], g_v[NTOK*DMODEL];
__device__ bf16  g_aoH[NTOK*DMODEL], g_aoL[NTOK*DMODEL];
__device__ float g_kc[LLAYERS][CSZ], g_vc[LLAYERS][CSZ];
__device__ float g_gq[LLAYERS][NB*DMODEL];
__device__ bf16  g_KinH[CSZ], g_KinL[CSZ], g_VinH[CSZ], g_VinL[CSZ];
__device__ bf16  g_gH[NB*DMODEL], g_gL[NB*DMODEL];
__device__ bf16  g_wTH[9*LLAYERS*WSZ], g_wTL[9*LLAYERS*WSZ];   // [N,K] transposed splits
__device__ bf16  g_wfTH[(size_t)NVOCAB*DMODEL], g_wfTL[(size_t)NVOCAB*DMODEL];
__device__ bf16  g_WosH[LLAYERS*WSZ], g_WosL[LLAYERS*WSZ];     // Wo_s raw row-major split
__device__ bf16  g_WocH[LLAYERS*WSZ], g_WocL[LLAYERS*WSZ];     // Wo_c raw row-major split
__device__ bf16  g_wscH[LLAYERS*WSZ], g_wscL[LLAYERS*WSZ];     // (Wo_s@Wq_c)^T hi/lo
__device__ bf16  g_wcbH[15*WSZ], g_wcbL[15*WSZ];               // (Wo_c[l]@W{q,k,v}_s[l+1])^T
__device__ bf16  g_wfcH[(size_t)NVOCAB*DMODEL], g_wfcL[(size_t)NVOCAB*DMODEL]; // (Wo_c[5]@Wf)^T

// ================= helpers =================
__device__ __forceinline__ uint32_t smem_to_u32(const void* p) {
    uint32_t a;
    asm("{ .reg .u64 t; cvta.to.shared.u64 t, %1; cvt.u32.u64 %0, t; }" : "=r"(a) : "l"(p));
    return a;
}
__device__ __forceinline__ void cp16(uint32_t dst, const void* src, bool p) {
    int sz = p ? 16 : 0;
    asm volatile("cp.async.cg.shared.global [%0], [%1], 16, %2;" :: "r"(dst), "l"(src), "r"(sz) : "memory");
}
#define CP_COMMIT() asm volatile("cp.async.commit_group;" ::: "memory")
#define CP_WAIT0()  asm volatile("cp.async.wait_group 0;" ::: "memory")
#define CP_WAIT1()  asm volatile("cp.async.wait_group 1;" ::: "memory")

__device__ __forceinline__ void ldm4(uint32_t addr, uint32_t* r) {
    asm volatile("ldmatrix.sync.aligned.m8n8.x4.shared.b16 {%0,%1,%2,%3}, [%4];"
        : "=r"(r[0]), "=r"(r[1]), "=r"(r[2]), "=r"(r[3]) : "r"(addr));
}
__device__ __forceinline__ void mma16816(float* c, const uint32_t* a, uint32_t b0, uint32_t b1) {
    asm volatile("mma.sync.aligned.m16n8k16.row.col.f32.bf16.bf16.f32 "
        "{%0,%1,%2,%3}, {%4,%5,%6,%7}, {%8,%9}, {%0,%1,%2,%3};"
        : "+f"(c[0]), "+f"(c[1]), "+f"(c[2]), "+f"(c[3])
        : "r"(a[0]), "r"(a[1]), "r"(a[2]), "r"(a[3]), "r"(b0), "r"(b1));
}
__device__ __forceinline__ void split2(float v, bf16& h, bf16& l) {
    h = __float2bfloat16(v);
    l = __float2bfloat16(v - __bfloat162float(h));
}

// ================= conversion kernels =================
union BPack { bf16 b[4]; uint2 u; };

__global__ void split_kernel(const float* __restrict__ src, bf16* __restrict__ h,
                             bf16* __restrict__ l, int n) {
    int i = (blockIdx.x * blockDim.x + threadIdx.x) * 4;
    if (i < n) {
        float4 v = *(const float4*)(src + i);
        BPack ph, pl;
        split2(v.x, ph.b[0], pl.b[0]);
        split2(v.y, ph.b[1], pl.b[1]);
        split2(v.z, ph.b[2], pl.b[2]);
        split2(v.w, ph.b[3], pl.b[3]);
        *(uint2*)(h + i) = ph.u;
        *(uint2*)(l + i) = pl.u;
    }
}

struct WPtrs { const float* p[9]; };

__global__ void wconv_all_kernel(WPtrs wp, bf16* __restrict__ Th, bf16* __restrict__ Tl) {
    __shared__ float t[32][33];
    const int z = blockIdx.z, m = z / LLAYERS, l = z % LLAYERS;
    const float* Wz = wp.p[m] + (size_t)l * WSZ;
    bf16* Thz = Th + ((size_t)m*LLAYERS + l) * WSZ;
    bf16* Tlz = Tl + ((size_t)m*LLAYERS + l) * WSZ;
    int n0 = blockIdx.x * 32, k0 = blockIdx.y * 32;
    int tx = threadIdx.x, ty = threadIdx.y;
    for (int r = ty; r < 32; r += 8) {
        t[r][tx] = Wz[(size_t)(k0 + r) * DMODEL + n0 + tx];
    }
    __syncthreads();
    for (int r = ty; r < 32; r += 8) {
        bf16 hh, ll; split2(t[tx][r], hh, ll);
        Thz[(size_t)(n0 + r) * DMODEL + k0 + tx] = hh;
        Tlz[(size_t)(n0 + r) * DMODEL + k0 + tx] = ll;
    }
}

__global__ void wconv_kernel(const float* __restrict__ W, bf16* __restrict__ Th,
                             bf16* __restrict__ Tl, int Kdim, int Ndim) {
    __shared__ float t[32][33];
    int n0 = blockIdx.x * 32, k0 = blockIdx.y * 32;
    int tx = threadIdx.x, ty = threadIdx.y;
    for (int r = ty; r < 32; r += 8) {
        int n = n0 + tx;
        t[r][tx] = (n < Ndim) ? W[(size_t)(k0 + r) * Ndim + n] : 0.f;
    }
    __syncthreads();
    for (int r = ty; r < 32; r += 8) {
        int n = n0 + r;
        if (n < Ndim) {
            bf16 hh, ll; split2(t[tx][r], hh, ll);
            Th[(size_t)n * Kdim + k0 + tx] = hh;
            Tl[(size_t)n * Kdim + k0 + tx] = ll;
        }
    }
}

// ================= embedding + positional encoding =================
__global__ void embed_kernel(const int* __restrict__ x, const float* __restrict__ emb,
                             bf16* __restrict__ outH, bf16* __restrict__ outL) {
    int t = blockIdx.x;
    int s = t % NS;
    int tok = x[t];
    for (int d = threadIdx.x; d < DMODEL; d += blockDim.x) {
        int j = d >> 1;
        float ang = (float)s * powf(10000.0f, -(2.0f*(float)j)/(float)DMODEL);
        float pe = (d & 1) ? cosf(ang) : sinf(ang);
        float v = emb[tok*DMODEL + d] + pe;
        bf16 hh, ll; split2(v, hh, ll);
        outH[t*DMODEL + d] = hh; outL[t*DMODEL + d] = ll;
    }
}

// ================= split-bf16 HMMA GEMM (K-chunk 32, templated stages) ========
#define NCHUNK   16
#define STRIDE   40
#define TILE_A   (128*STRIDE*2)
template<int NT, int STAGES> struct TileCfg {
    static const int TB  = NT*STRIDE*2;
    static const int BUF = 2*TILE_A + 2*TB;
    static const int SMEM = STAGES*BUF;
    static const int NP  = NT/32;
};

template<int NT, int STAGES>
__device__ __forceinline__ void load_tiles(
    const bf16* __restrict__ Ah, const bf16* __restrict__ Al,
    const bf16* __restrict__ Bh, const bf16* __restrict__ Bl,
    int M, int N, int m0, int n0, int ch, uint32_t sbuf, int tid)
{
    typedef TileCfg<NT, STAGES> TC;
    {
        const int row = tid >> 1;
        const int qd  = (tid & 1) * 2;
        const uint32_t sof = sbuf + (uint32_t)(row*STRIDE + qd*8) * 2;
        bool ok = (m0 + row) < M;
        const bf16* pa = Ah + (size_t)(m0 + row) * 512 + ch*32 + qd*8;
        const bf16* pl = Al + (size_t)(m0 + row) * 512 + ch*32 + qd*8;
        cp16(sof,                pa,     ok);
        cp16(sof + 16,           pa + 8, ok);
        cp16(sof + TILE_A,       pl,     ok);
        cp16(sof + TILE_A + 16,  pl + 8, ok);
    }
    if (NT == 128) {
        const int row = tid >> 1;
        const int qd  = (tid & 1) * 2;
        const uint32_t sof = sbuf + 2*TILE_A + (uint32_t)(row*STRIDE + qd*8) * 2;
        bool ok = (n0 + row) < N;
        const bf16* pb = Bh + (size_t)(n0 + row) * 512 + ch*32 + qd*8;
        const bf16* pl = Bl + (size_t)(n0 + row) * 512 + ch*32 + qd*8;
        cp16(sof,            pb,     ok);
        cp16(sof + 16,       pb + 8, ok);
        cp16(sof + TC::TB,       pl,     ok);
        cp16(sof + TC::TB + 16,  pl + 8, ok);
    } else {
        const int row = tid >> 2;
        const int qd  = tid & 3;
        const uint32_t sof = sbuf + 2*TILE_A + (uint32_t)(row*STRIDE + qd*8) * 2;
        bool ok = (n0 + row) < N;
        cp16(sof,            Bh + (size_t)(n0 + row) * 512 + ch*32 + qd*8, ok);
        cp16(sof + TC::TB,   Bl + (size_t)(n0 + row) * 512 + ch*32 + qd*8, ok);
    }
}

template<int NT, int STAGES>
__device__ void gemm_core(const bf16* __restrict__ Ah, const bf16* __restrict__ Al,
                          const bf16* __restrict__ Bh, const bf16* __restrict__ Bl,
                          float* __restrict__ C, bf16* __restrict__ Ch, bf16* __restrict__ Cl,
                          int M, int N,
                          const float* __restrict__ rowBias, const float* __restrict__ colBias)
{
    typedef TileCfg<NT, STAGES> TC;
    extern __shared__ char smem[];
    const uint32_t sb = smem_to_u32(smem);
    const int tid = threadIdx.x, wid = tid >> 5, lane = tid & 31;
    const int wm = wid & 3, wn = wid >> 2;
    const int m0 = blockIdx.y * 128, n0 = blockIdx.x * NT;
    const int NP = TC::NP;
    const int BUF = TC::BUF;
    const int TB = TC::TB;

    float acc[2][2*TC::NP][4];
    #pragma unroll
    for (int i = 0; i < 2; i++)
        #pragma unroll
        for (int j = 0; j < 2*NP; j++)
            #pragma unroll
            for (int e = 0; e < 4; e++) acc[i][j][e] = 0.f;

    #pragma unroll
    for (int s = 0; s < STAGES-1; s++) {
        load_tiles<NT, STAGES>(Ah, Al, Bh, Bl, M, N, m0, n0, s, sb + s*BUF, tid);
        CP_COMMIT();
    }

    int cur = 0;
    const int aRow = (lane & 15);
    const int aCol = (lane >> 4) << 3;
    const int bRow = (lane & 7) + (((lane >> 4) & 1) << 3);
    const int bCol = ((lane >> 3) & 1) << 3;

    #pragma unroll 1
    for (int ch = 0; ch < NCHUNK; ch++) {
        if (STAGES == 3 && ch < NCHUNK-1) { CP_WAIT1(); } else { CP_WAIT0(); }
        __syncthreads();
        if (ch + STAGES - 1 < NCHUNK) {
            int nb = cur + STAGES - 1; if (nb >= STAGES) nb -= STAGES;
            load_tiles<NT, STAGES>(Ah, Al, Bh, Bl, M, N, m0, n0, ch + STAGES - 1, sb + nb*BUF, tid);
            CP_COMMIT();
        }
        const uint32_t sAh = sb + cur*BUF;
        const uint32_t sAl = sAh + TILE_A;
        const uint32_t sBh = sAh + 2*TILE_A;
        const uint32_t sBl = sBh + TB;

        #pragma unroll
        for (int k16 = 0; k16 < 32; k16 += 16) {
            uint32_t ah[8], al[8];
            uint32_t bh[TC::NP][4], bl[TC::NP][4];
            {
                uint32_t a0 = (uint32_t)((wm*32 + aRow)*STRIDE + k16 + aCol) * 2;
                uint32_t a1 = (uint32_t)((wm*32 + 16 + aRow)*STRIDE + k16 + aCol) * 2;
                ldm4(sAh + a0, ah);  ldm4(sAh + a1, ah + 4);
                ldm4(sAl + a0, al);  ldm4(sAl + a1, al + 4);
            }
            #pragma unroll
            for (int np = 0; np < NP; np++) {
                const int nb2 = wn*(NT/2) + np*16;
                const uint32_t boff = (uint32_t)((nb2 + bRow)*STRIDE + k16 + bCol) * 2;
                ldm4(sBh + boff, bh[np]);
                ldm4(sBl + boff, bl[np]);
            }
            #pragma unroll
            for (int np = 0; np < NP; np++)
                #pragma unroll
                for (int mi = 0; mi < 2; mi++) {
                    mma16816(acc[mi][np*2],     ah + 4*mi, bh[np][0], bh[np][1]);
                    mma16816(acc[mi][np*2 + 1], ah + 4*mi, bh[np][2], bh[np][3]);
                }
            #pragma unroll
            for (int np = 0; np < NP; np++)
                #pragma unroll
                for (int mi = 0; mi < 2; mi++) {
                    mma16816(acc[mi][np*2],     ah + 4*mi, bl[np][0], bl[np][1]);
                    mma16816(acc[mi][np*2 + 1], ah + 4*mi, bl[np][2], bl[np][3]);
                }
            #pragma unroll
            for (int np = 0; np < NP; np++)
                #pragma unroll
                for (int mi = 0; mi < 2; mi++) {
                    mma16816(acc[mi][np*2],     al + 4*mi, bh[np][0], bh[np][1]);
                    mma16816(acc[mi][np*2 + 1], al + 4*mi, bh[np][2], bh[np][3]);
                }
        }
        cur++; if (cur == STAGES) cur = 0;
    }

    // epilogue
    const int r0 = m0 + wm*32 + (lane >> 2);
    const int c0 = n0 + wn*(NT/2) + (lane & 3) * 2;
    #pragma unroll
    for (int mi = 0; mi < 2; mi++) {
        #pragma unroll
        for (int na = 0; na < 2*NP; na++) {
            const int col = c0 + (na >> 1)*16 + (na & 1)*8;
            #pragma unroll
            for (int e = 0; e < 4; e++) {
                const int r = r0 + mi*16 + ((e >> 1) << 3);
                const int c = col + (e & 1);
                if (r >= M || c >= N) continue;
                float v = acc[mi][na][e];
                if (rowBias) v += rowBias[(size_t)(r >> 6) * N + c];
                if (colBias) v += colBias[c];
                if (C) C[(size_t)r * N + c] = v;
                if (Ch) {
                    bf16 hh, ll; split2(v, hh, ll);
                    Ch[(size_t)r * N + c] = hh;
                    Cl[(size_t)r * N + c] = ll;
                }
            }
        }
    }
}

#define SMEM64  (TileCfg<64,3>::SMEM)     // 92160 B
#define SMEM128 (TileCfg<128,2>::SMEM)    // 81920 B

__global__ void __launch_bounds__(256, 2) gemm_plain64(
    const bf16* Ah, const bf16* Al, const bf16* Bh, const bf16* Bl,
    float* C, bf16* Ch, bf16* Cl, int M, int N,
    const float* rowBias, const float* colBias) {
    gemm_core<64,3>(Ah, Al, Bh, Bl, C, Ch, Cl, M, N, rowBias, colBias);
}

__global__ void __launch_bounds__(256, 2) gemm_final128(
    const bf16* Ah, const bf16* Al, const bf16* Bh, const bf16* Bl,
    float* C, int M, int N, const float* colBias) {
    gemm_core<128,2>(Ah, Al, Bh, Bl, C, nullptr, nullptr, M, N, nullptr, colBias);
}

// layer-0 QKV from embedding activations (original weights)
__global__ void __launch_bounds__(256, 2) gemm_qkv3(
    const bf16* Ah, const bf16* Al, const bf16* wTH, const bf16* wTL,
    float* q, float* k, float* v) {
    const int z = blockIdx.z;
    const size_t off = (size_t)z*LLAYERS * WSZ;   // layer 0 of ids 0,1,2
    float* C = (z == 0) ? q : (z == 1) ? k : v;
    gemm_core<64,3>(Ah, Al, wTH + off, wTL + off, C, nullptr, nullptr, NTOK, DMODEL, nullptr, nullptr);
}

// combined QKV for layer l+1: qkv = ao_c @ (Wo_c[l] @ W{q,k,v}_s[l+1])
__global__ void __launch_bounds__(256, 2) gemm_qkv3c(
    const bf16* Ah, const bf16* Al, const bf16* WcH, const bf16* WcL, int l,
    float* q, float* k, float* v) {
    const int z = blockIdx.z;
    const size_t off = ((size_t)(l*3 + z)) * WSZ;
    float* C = (z == 0) ? q : (z == 1) ? k : v;
    gemm_core<64,3>(Ah, Al, WcH + off, WcL + off, C, nullptr, nullptr, NTOK, DMODEL, nullptr, nullptr);
}

// WscT[l] = (Wo_s[l] @ Wq_c[l])^T : A = Wq_c^T split, B = Wo_s raw split
__global__ void __launch_bounds__(256, 2) gemm_wsc6(
    const bf16* wTH, const bf16* wTL, const bf16* WosH, const bf16* WosL,
    bf16* wscH, bf16* wscL) {
    const int l = blockIdx.z;
    const size_t aoff = ((size_t)4*LLAYERS + l) * WSZ;
    const size_t boff = (size_t)l * WSZ;
    gemm_core<64,3>(wTH + aoff, wTL + aoff, WosH + boff, WosL + boff,
                    nullptr, wscH + boff, wscL + boff, DMODEL, DMODEL, nullptr, nullptr);
}

// Wcb[l*3+m] = (Wo_c[l] @ W{q,k,v}_s[l+1])^T : A = W{q,k,v}_s[l+1]^T, B = Wo_c[l] raw
__global__ void __launch_bounds__(256, 2) gemm_comb15(
    const bf16* wTH, const bf16* wTL, const bf16* WocH, const bf16* WocL,
    bf16* WcH, bf16* WcL) {
    const int z = blockIdx.z, l = z / 3, m = z % 3;
    const size_t aoff = ((size_t)m*LLAYERS + (l+1)) * WSZ;
    const size_t boff = (size_t)l * WSZ;
    gemm_core<64,3>(wTH + aoff, wTL + aoff, WocH + boff, WocL + boff,
                    nullptr, WcH + (size_t)z*WSZ, WcL + (size_t)z*WSZ, DMODEL, DMODEL, nullptr, nullptr);
}

// WfC = (Wo_c[5] @ Wf)^T [10000, 512] : A = Wf^T split, B = Wo_c[5] raw
__global__ void __launch_bounds__(256, 2) gemm_wfc(
    const bf16* wfTH, const bf16* wfTL, const bf16* WocH, const bf16* WocL,
    bf16* wfcH, bf16* wfcL) {
    const size_t boff = (size_t)(LLAYERS-1) * WSZ;
    gemm_core<64,3>(wfTH, wfTL, WocH + boff, WocL + boff,
                    nullptr, wfcH, wfcL, NVOCAB, DMODEL, nullptr, nullptr);
}

__global__ void __launch_bounds__(256, 2) gemm_cross2(
    const bf16* KinH, const bf16* KinL, const bf16* VinH, const bf16* VinL,
    const bf16* wTH, const bf16* wTL, int l, float* kc, float* vc) {
    const int kv = blockIdx.z;
    const size_t woff = ((size_t)(6 + kv)*LLAYERS + l) * WSZ;
    gemm_core<128,2>(kv ? VinH : KinH, kv ? VinL : KinL, wTH + woff, wTL + woff,
                     kv ? vc : kc, nullptr, nullptr, NCTOK, DMODEL, nullptr, nullptr);
}

__global__ void __launch_bounds__(256, 2) gemm_gq6(
    const bf16* gH, const bf16* gL, const bf16* wTH, const bf16* wTL, float* gq) {
    const int l = blockIdx.z;
    const size_t woff = ((size_t)5*LLAYERS + l) * WSZ;
    gemm_core<64,3>(gH, gL, wTH + woff, wTL + woff,
                    gq + (size_t)l*NB*DMODEL, nullptr, nullptr, NB, DMODEL, nullptr, nullptr);
}

// ================= fused attention (fp32, register-blocked), writes hi/lo ======
#define ATTN_SMEM_FLOATS (3*64*65 + 8*512)
template<bool CAUSAL>
__global__ void attn_kernel(const float* __restrict__ Q, const float* __restrict__ Kb,
                            const float* __restrict__ Vb,
                            bf16* __restrict__ Oh, bf16* __restrict__ Ol,
                            int skeys, int kvTokens) {
    extern __shared__ float sm[];
    float* Qs = sm;
    float* Ks = sm + 64*65;
    float* Vs = sm + 2*64*65;
    float* Ps = sm + 3*64*65;

    const int b = blockIdx.x / NH, h = blockIdx.x % NH;
    const int tid = threadIdx.x, w = tid >> 5, lane = tid & 31;

    for (int i = tid; i < 64*64; i += 256) {
        int r = i >> 6, c = i & 63;
        Qs[r*65 + c] = Q[(size_t)(b*NS + r)*DMODEL + h*HD + c];
    }
    float mrow[8], lrow[8], a0[8], a1[8];
    #pragma unroll
    for (int i = 0; i < 8; i++) { mrow[i] = -1e30f; lrow[i] = 0.f; a0[i] = 0.f; a1[i] = 0.f; }
    __syncthreads();

    const int nch = (skeys + 63) >> 6;
    for (int ch = 0; ch < nch; ch++) {
        const int kb = ch * 64;
        const int cnt = min(64, skeys - kb);
        for (int i = tid; i < 64*64; i += 256) {
            int r = i >> 6, c = i & 63;
            float kv = 0.f, vv = 0.f;
            if (r < cnt) {
                size_t off = (size_t)(b*kvTokens + kb + r)*DMODEL + h*HD + c;
                kv = Kb[off]; vv = Vb[off];
            }
            Ks[r*65 + c] = kv; Vs[r*65 + c] = vv;
        }
        __syncthreads();

        float d0[8], d1[8];
        #pragma unroll
        for (int i = 0; i < 8; i++) { d0[i] = 0.f; d1[i] = 0.f; }
        #pragma unroll 4
        for (int d = 0; d < 64; d++) {
            float k0 = Ks[lane*65 + d];
            float k1 = Ks[(lane+32)*65 + d];
            #pragma unroll
            for (int rr = 0; rr < 8; rr++) {
                float qv = Qs[(w*8 + rr)*65 + d];
                d0[rr] += qv * k0;
                d1[rr] += qv * k1;
            }
        }

        #pragma unroll
        for (int rr = 0; rr < 8; rr++) {
            const int r = w*8 + rr;
            float s0 = d0[rr] * 0.125f, s1 = d1[rr] * 0.125f;
            bool v0 = (lane      < cnt) && (!CAUSAL || (kb + lane)      <= r);
            bool v1 = (lane + 32 < cnt) && (!CAUSAL || (kb + lane + 32) <= r);
            if (!v0) s0 = -1e30f;
            if (!v1) s1 = -1e30f;
            float cm = fmaxf(s0, s1);
            #pragma unroll
            for (int o = 16; o > 0; o >>= 1) cm = fmaxf(cm, __shfl_xor_sync(0xffffffffu, cm, o));
            float nm = fmaxf(mrow[rr], cm);
            float corr = __expf(mrow[rr] - nm);
            float p0 = v0 ? __expf(s0 - nm) : 0.f;
            float p1 = v1 ? __expf(s1 - nm) : 0.f;
            float ps = p0 + p1;
            #pragma unroll
            for (int o = 16; o > 0; o >>= 1) ps += __shfl_xor_sync(0xffffffffu, ps, o);
            lrow[rr] = lrow[rr]*corr + ps;
            mrow[rr] = nm;
            a0[rr] *= corr; a1[rr] *= corr;
            Ps[w*512 + rr*64 + lane]      = p0;
            Ps[w*512 + rr*64 + lane + 32] = p1;
        }
        __syncwarp();

        #pragma unroll 4
        for (int kk = 0; kk < 64; kk++) {
            float v0 = Vs[kk*65 + lane];
            float v1 = Vs[kk*65 + lane + 32];
            #pragma unroll
            for (int rr = 0; rr < 8; rr++) {
                float p = Ps[w*512 + rr*64 + kk];
                a0[rr] += p * v0;
                a1[rr] += p * v1;
            }
        }
        __syncwarp();
        __syncthreads();
    }
    #pragma unroll
    for (int rr = 0; rr < 8; rr++) {
        int r = w*8 + rr;
        float inv = 1.0f / lrow[rr];
        size_t o = (size_t)(b*NS + r)*DMODEL + h*HD;
        float v0 = a0[rr] * inv, v1 = a1[rr] * inv;
        bf16 hh, ll;
        split2(v0, hh, ll); Oh[o + lane]      = hh; Ol[o + lane]      = ll;
        split2(v1, hh, ll); Oh[o + lane + 32] = hh; Ol[o + lane + 32] = ll;
    }
}

// ================= final row softmax over VOCAB (in-place) =================
__global__ void softmax_kernel(float* __restrict__ out) {
    __shared__ float buf[NVOCAB];
    __shared__ float red[8];
    const int tid = threadIdx.x, w = tid >> 5, lane = tid & 31;
    float* p = out + (size_t)blockIdx.x * NVOCAB;

    float mx = -1e30f;
    for (int i = tid; i < NVOCAB; i += 256) { float v = p[i]; buf[i] = v; mx = fmaxf(mx, v); }
    #pragma unroll
    for (int o = 16; o > 0; o >>= 1) mx = fmaxf(mx, __shfl_xor_sync(0xffffffffu, mx, o));
    if (lane == 0) red[w] = mx;
    __syncthreads();
    mx = red[0];
    #pragma unroll
    for (int i = 1; i < 8; i++) mx = fmaxf(mx, red[i]);
    __syncthreads();

    float sum = 0.f;
    for (int i = tid; i < NVOCAB; i += 256) { float e = __expf(buf[i] - mx); buf[i] = e; sum += e; }
    #pragma unroll
    for (int o = 16; o > 0; o >>= 1) sum += __shfl_xor_sync(0xffffffffu, sum, o);
    if (lane == 0) red[w] = sum;
    __syncthreads();
    sum = 0.f;
    #pragma unroll
    for (int i = 0; i < 8; i++) sum += red[i];
    float inv = 1.0f / sum;
    for (int i = tid; i < NVOCAB; i += 256) p[i] = buf[i] * inv;
}

// ================= host launcher =================
extern "C" void kernel_launch(void* const* d_in, const int* in_sizes, int n_in,
                              void* d_out, int out_size) {
    const int*   x   = (const int*)  d_in[0];
    const float* Kin = (const float*)d_in[1];
    const float* Vin = (const float*)d_in[2];
    const float* g   = (const float*)d_in[3];
    int i = 4;
    if (i < n_in && in_sizes[i] == 1) i++;
    const float* emb  = (const float*)d_in[i++];
    const float* Wq_s = (const float*)d_in[i++];
    const float* Wk_s = (const float*)d_in[i++];
    const float* Wv_s = (const float*)d_in[i++];
    const float* Wo_s = (const float*)d_in[i++];
    const float* Wq_c = (const float*)d_in[i++];
    const float* Wg_c = (const float*)d_in[i++];
    const float* Wk_c = (const float*)d_in[i++];
    const float* Wv_c = (const float*)d_in[i++];
    const float* Wo_c = (const float*)d_in[i++];
    const float* Wf   = (const float*)d_in[i++];
    const float* bf   = (const float*)d_in[i++];

    bf16 *actH, *actL, *aoH, *aoL, *KinH, *KinL, *VinH, *VinL, *gH, *gL;
    bf16 *wTH, *wTL, *wfTH, *wfTL, *WosH, *WosL, *WocH, *WocL;
    bf16 *wscH, *wscL, *wcbH, *wcbL, *wfcH, *wfcL;
    float *q, *k, *v, *kc, *vc, *gq;
    cudaGetSymbolAddress((void**)&actH, g_actH);  cudaGetSymbolAddress((void**)&actL, g_actL);
    cudaGetSymbolAddress((void**)&aoH,  g_aoH);   cudaGetSymbolAddress((void**)&aoL,  g_aoL);
    cudaGetSymbolAddress((void**)&KinH, g_KinH);  cudaGetSymbolAddress((void**)&KinL, g_KinL);
    cudaGetSymbolAddress((void**)&VinH, g_VinH);  cudaGetSymbolAddress((void**)&VinL, g_VinL);
    cudaGetSymbolAddress((void**)&gH,   g_gH);    cudaGetSymbolAddress((void**)&gL,   g_gL);
    cudaGetSymbolAddress((void**)&wTH,  g_wTH);   cudaGetSymbolAddress((void**)&wTL,  g_wTL);
    cudaGetSymbolAddress((void**)&wfTH, g_wfTH);  cudaGetSymbolAddress((void**)&wfTL, g_wfTL);
    cudaGetSymbolAddress((void**)&WosH, g_WosH);  cudaGetSymbolAddress((void**)&WosL, g_WosL);
    cudaGetSymbolAddress((void**)&WocH, g_WocH);  cudaGetSymbolAddress((void**)&WocL, g_WocL);
    cudaGetSymbolAddress((void**)&wscH, g_wscH);  cudaGetSymbolAddress((void**)&wscL, g_wscL);
    cudaGetSymbolAddress((void**)&wcbH, g_wcbH);  cudaGetSymbolAddress((void**)&wcbL, g_wcbL);
    cudaGetSymbolAddress((void**)&wfcH, g_wfcH);  cudaGetSymbolAddress((void**)&wfcL, g_wfcL);
    cudaGetSymbolAddress((void**)&q,  g_q);  cudaGetSymbolAddress((void**)&k, g_k);
    cudaGetSymbolAddress((void**)&v,  g_v);
    cudaGetSymbolAddress((void**)&kc, g_kc); cudaGetSymbolAddress((void**)&vc, g_vc);
    cudaGetSymbolAddress((void**)&gq, g_gq);

    static cudaStream_t sAux = nullptr;
    static cudaEvent_t eFork = nullptr, eWf = nullptr, ePre = nullptr, eComb = nullptr, eCross[LLAYERS];
    if (!sAux) {
        cudaStreamCreateWithFlags(&sAux, cudaStreamNonBlocking);
        cudaEventCreateWithFlags(&eFork, cudaEventDisableTiming);
        cudaEventCreateWithFlags(&eWf,   cudaEventDisableTiming);
        cudaEventCreateWithFlags(&ePre,  cudaEventDisableTiming);
        cudaEventCreateWithFlags(&eComb, cudaEventDisableTiming);
        for (int l = 0; l < LLAYERS; l++)
            cudaEventCreateWithFlags(&eCross[l], cudaEventDisableTiming);
    }

    const int ATTN_SMEM = ATTN_SMEM_FLOATS * (int)sizeof(float);
    cudaFuncSetAttribute(attn_kernel<true>,  cudaFuncAttributeMaxDynamicSharedMemorySize, ATTN_SMEM);
    cudaFuncSetAttribute(attn_kernel<false>, cudaFuncAttributeMaxDynamicSharedMemorySize, ATTN_SMEM);
    cudaFuncSetAttribute(gemm_plain64,  cudaFuncAttributeMaxDynamicSharedMemorySize, SMEM64);
    cudaFuncSetAttribute(gemm_qkv3,     cudaFuncAttributeMaxDynamicSharedMemorySize, SMEM64);
    cudaFuncSetAttribute(gemm_qkv3c,    cudaFuncAttributeMaxDynamicSharedMemorySize, SMEM64);
    cudaFuncSetAttribute(gemm_gq6,      cudaFuncAttributeMaxDynamicSharedMemorySize, SMEM64);
    cudaFuncSetAttribute(gemm_wsc6,     cudaFuncAttributeMaxDynamicSharedMemorySize, SMEM64);
    cudaFuncSetAttribute(gemm_comb15,   cudaFuncAttributeMaxDynamicSharedMemorySize, SMEM64);
    cudaFuncSetAttribute(gemm_wfc,      cudaFuncAttributeMaxDynamicSharedMemorySize, SMEM64);
    cudaFuncSetAttribute(gemm_cross2,   cudaFuncAttributeMaxDynamicSharedMemorySize, SMEM128);
    cudaFuncSetAttribute(gemm_final128, cudaFuncAttributeMaxDynamicSharedMemorySize, SMEM128);

    // ---- main stream: weight conversions + input splits ----
    WPtrs wp;
    wp.p[0]=Wq_s; wp.p[1]=Wk_s; wp.p[2]=Wv_s; wp.p[3]=Wo_s; wp.p[4]=Wq_c;
    wp.p[5]=Wg_c; wp.p[6]=Wk_c; wp.p[7]=Wv_c; wp.p[8]=Wo_c;
    wconv_all_kernel<<<dim3(16, 16, 9*LLAYERS), dim3(32, 8)>>>(wp, wTH, wTL);
    split_kernel<<<((int)(LLAYERS*WSZ)/4 + 255)/256, 256>>>(Wo_s, WosH, WosL, (int)(LLAYERS*WSZ));
    split_kernel<<<((int)(LLAYERS*WSZ)/4 + 255)/256, 256>>>(Wo_c, WocH, WocL, (int)(LLAYERS*WSZ));
    split_kernel<<<((int)CSZ/4 + 255)/256, 256>>>(Kin, KinH, KinL, (int)CSZ);
    split_kernel<<<((int)CSZ/4 + 255)/256, 256>>>(Vin, VinH, VinL, (int)CSZ);
    split_kernel<<<(NB*DMODEL/4 + 255)/256, 256>>>(g, gH, gL, NB*DMODEL);

    // ---- fork aux stream ----
    cudaEventRecord(eFork, 0);
    cudaStreamWaitEvent(sAux, eFork, 0);
    gemm_wsc6<<<dim3(8, 4, LLAYERS), 256, SMEM64, sAux>>>(wTH, wTL, WosH, WosL, wscH, wscL);
    gemm_gq6 <<<dim3(8, 1, LLAYERS), 256, SMEM64, sAux>>>(gH, gL, wTH, wTL, gq);
    cudaEventRecord(ePre, sAux);
    gemm_cross2<<<dim3(4, NCTOK/128, 2), 256, SMEM128, sAux>>>(
        KinH, KinL, VinH, VinL, wTH, wTL, 0, kc, vc);
    cudaEventRecord(eCross[0], sAux);
    gemm_comb15<<<dim3(8, 4, 15), 256, SMEM64, sAux>>>(wTH, wTL, WocH, WocL, wcbH, wcbL);
    cudaEventRecord(eComb, sAux);
    for (int l = 1; l < LLAYERS; l++) {
        gemm_cross2<<<dim3(4, NCTOK/128, 2), 256, SMEM128, sAux>>>(
            KinH, KinL, VinH, VinL, wTH, wTL, l,
            kc + (size_t)l*CSZ, vc + (size_t)l*CSZ);
        cudaEventRecord(eCross[l], sAux);
    }
    wconv_kernel<<<dim3((NVOCAB + 31)/32, 16, 1), dim3(32, 8), 0, sAux>>>(
        Wf, wfTH, wfTL, DMODEL, NVOCAB);
    gemm_wfc<<<dim3(8, (NVOCAB + 127)/128), 256, SMEM64, sAux>>>(
        wfTH, wfTL, WocH, WocL, wfcH, wfcL);
    cudaEventRecord(eWf, sAux);

    // ---- main stream: embedding + layer loop ----
    embed_kernel<<<NTOK, 128>>>(x, emb, actH, actL);
    cudaStreamWaitEvent(0, ePre, 0);   // gq + Wsc ready
    gemm_qkv3<<<dim3(8, NTOK/128, 3), 256, SMEM64>>>(actH, actL, wTH, wTL, q, k, v);

    for (int l = 0; l < LLAYERS; l++) {
        attn_kernel<true><<<NB*NH, 256, ATTN_SMEM>>>(q, k, v, aoH, aoL, NS, NS);
        // fused (Wo_s @ Wq_c) projection: q = ao_s @ Wsc + gq
        gemm_plain64<<<dim3(8, NTOK/128), 256, SMEM64>>>(
            aoH, aoL, wscH + (size_t)l*WSZ, wscL + (size_t)l*WSZ,
            q, nullptr, nullptr, NTOK, DMODEL, gq + (size_t)l*NB*DMODEL, nullptr);
        cudaStreamWaitEvent(0, eCross[l], 0);
        attn_kernel<false><<<NB*NH, 256, ATTN_SMEM>>>(
            q, kc + (size_t)l*CSZ, vc + (size_t)l*CSZ, aoH, aoL, NNR, NNR);
        if (l + 1 < LLAYERS) {
            if (l == 0) cudaStreamWaitEvent(0, eComb, 0);
            // fused (Wo_c @ W{q,k,v}_s) projection for next layer
            gemm_qkv3c<<<dim3(8, NTOK/128, 3), 256, SMEM64>>>(aoH, aoL, wcbH, wcbL, l, q, k, v);
        }
    }

    // ---- final: logits = ao_c @ (Wo_c[5] @ Wf) + bf ----
    cudaStreamWaitEvent(0, eWf, 0);
    gemm_final128<<<dim3((NVOCAB + 127)/128, NTOK/128), 256, SMEM128>>>(
        aoH, aoL, wfcH, wfcL, (float*)d_out, NTOK, NVOCAB, bf);
    softmax_kernel<<<NTOK, 256>>>((float*)d_out);
}

// round 16
// speedup vs baseline: 1.1152x; 1.0207x over previous
#include <cuda_runtime.h>
#include <cuda_bf16.h>
#include <math.h>
#include <stdint.h>

typedef __nv_bfloat16 bf16;

#define LLAYERS 6
#define DMODEL  512
#define NH      8
#define HD      64
#define NVOCAB  10000
#define NB      32
#define NS      64
#define NNR     196
#define NTOK    (NB*NS)     // 2048
#define NCTOK   (NB*NNR)    // 6272
#define WSZ     ((size_t)DMODEL*DMODEL)
#define CSZ     ((size_t)NCTOK*DMODEL)

// ================= scratch =================
__device__ bf16  g_actH[NTOK*DMODEL], g_actL[NTOK*DMODEL];
__device__ float g_q[NTOK*DMODEL], g_k[NTOK*DMODEL], g_v[NTOK*DMODEL];
__device__ bf16  g_aoH[NTOK*DMODEL], g_aoL[NTOK*DMODEL];
__device__ float g_kc[LLAYERS][CSZ], g_vc[LLAYERS][CSZ];
__device__ float g_gq[LLAYERS][NB*DMODEL];
__device__ bf16  g_KinH[CSZ], g_KinL[CSZ], g_VinH[CSZ], g_VinL[CSZ];
__device__ bf16  g_gH[NB*DMODEL], g_gL[NB*DMODEL];
__device__ bf16  g_wTH[9*LLAYERS*WSZ], g_wTL[9*LLAYERS*WSZ];   // [N,K] transposed splits
__device__ bf16  g_wfTH[(size_t)NVOCAB*DMODEL], g_wfTL[(size_t)NVOCAB*DMODEL];
__device__ bf16  g_WosH[LLAYERS*WSZ], g_WosL[LLAYERS*WSZ];     // Wo_s raw row-major split
__device__ bf16  g_WocH[LLAYERS*WSZ], g_WocL[LLAYERS*WSZ];     // Wo_c raw row-major split
__device__ bf16  g_wscH[LLAYERS*WSZ], g_wscL[LLAYERS*WSZ];     // (Wo_s@Wq_c)^T hi/lo
__device__ bf16  g_wcbH[15*WSZ], g_wcbL[15*WSZ];               // (Wo_c[l]@W{q,k,v}_s[l+1])^T
__device__ bf16  g_wfcH[(size_t)NVOCAB*DMODEL], g_wfcL[(size_t)NVOCAB*DMODEL]; // (Wo_c[5]@Wf)^T

// ================= helpers =================
__device__ __forceinline__ uint32_t smem_to_u32(const void* p) {
    uint32_t a;
    asm("{ .reg .u64 t; cvta.to.shared.u64 t, %1; cvt.u32.u64 %0, t; }" : "=r"(a) : "l"(p));
    return a;
}
__device__ __forceinline__ void cp16(uint32_t dst, const void* src, bool p) {
    int sz = p ? 16 : 0;
    asm volatile("cp.async.cg.shared.global [%0], [%1], 16, %2;" :: "r"(dst), "l"(src), "r"(sz) : "memory");
}
#define CP_COMMIT() asm volatile("cp.async.commit_group;" ::: "memory")
#define CP_WAIT0()  asm volatile("cp.async.wait_group 0;" ::: "memory")
#define CP_WAIT1()  asm volatile("cp.async.wait_group 1;" ::: "memory")

__device__ __forceinline__ void ldm4(uint32_t addr, uint32_t* r) {
    asm volatile("ldmatrix.sync.aligned.m8n8.x4.shared.b16 {%0,%1,%2,%3}, [%4];"
        : "=r"(r[0]), "=r"(r[1]), "=r"(r[2]), "=r"(r[3]) : "r"(addr));
}
__device__ __forceinline__ void mma16816(float* c, const uint32_t* a, uint32_t b0, uint32_t b1) {
    asm volatile("mma.sync.aligned.m16n8k16.row.col.f32.bf16.bf16.f32 "
        "{%0,%1,%2,%3}, {%4,%5,%6,%7}, {%8,%9}, {%0,%1,%2,%3};"
        : "+f"(c[0]), "+f"(c[1]), "+f"(c[2]), "+f"(c[3])
        : "r"(a[0]), "r"(a[1]), "r"(a[2]), "r"(a[3]), "r"(b0), "r"(b1));
}
__device__ __forceinline__ void split2(float v, bf16& h, bf16& l) {
    h = __float2bfloat16(v);
    l = __float2bfloat16(v - __bfloat162float(h));
}

// ================= conversion kernels =================
union BPack { bf16 b[4]; uint2 u; };

__global__ void split_kernel(const float* __restrict__ src, bf16* __restrict__ h,
                             bf16* __restrict__ l, int n) {
    int i = (blockIdx.x * blockDim.x + threadIdx.x) * 4;
    if (i < n) {
        float4 v = *(const float4*)(src + i);
        BPack ph, pl;
        split2(v.x, ph.b[0], pl.b[0]);
        split2(v.y, ph.b[1], pl.b[1]);
        split2(v.z, ph.b[2], pl.b[2]);
        split2(v.w, ph.b[3], pl.b[3]);
        *(uint2*)(h + i) = ph.u;
        *(uint2*)(l + i) = pl.u;
    }
}

struct WPtrs { const float* p[9]; };

__global__ void wconv_all_kernel(WPtrs wp, bf16* __restrict__ Th, bf16* __restrict__ Tl) {
    __shared__ float t[32][33];
    const int z = blockIdx.z, m = z / LLAYERS, l = z % LLAYERS;
    const float* Wz = wp.p[m] + (size_t)l * WSZ;
    bf16* Thz = Th + ((size_t)m*LLAYERS + l) * WSZ;
    bf16* Tlz = Tl + ((size_t)m*LLAYERS + l) * WSZ;
    int n0 = blockIdx.x * 32, k0 = blockIdx.y * 32;
    int tx = threadIdx.x, ty = threadIdx.y;
    for (int r = ty; r < 32; r += 8) {
        t[r][tx] = Wz[(size_t)(k0 + r) * DMODEL + n0 + tx];
    }
    __syncthreads();
    for (int r = ty; r < 32; r += 8) {
        bf16 hh, ll; split2(t[tx][r], hh, ll);
        Thz[(size_t)(n0 + r) * DMODEL + k0 + tx] = hh;
        Tlz[(size_t)(n0 + r) * DMODEL + k0 + tx] = ll;
    }
}

__global__ void wconv_kernel(const float* __restrict__ W, bf16* __restrict__ Th,
                             bf16* __restrict__ Tl, int Kdim, int Ndim) {
    __shared__ float t[32][33];
    int n0 = blockIdx.x * 32, k0 = blockIdx.y * 32;
    int tx = threadIdx.x, ty = threadIdx.y;
    for (int r = ty; r < 32; r += 8) {
        int n = n0 + tx;
        t[r][tx] = (n < Ndim) ? W[(size_t)(k0 + r) * Ndim + n] : 0.f;
    }
    __syncthreads();
    for (int r = ty; r < 32; r += 8) {
        int n = n0 + r;
        if (n < Ndim) {
            bf16 hh, ll; split2(t[tx][r], hh, ll);
            Th[(size_t)n * Kdim + k0 + tx] = hh;
            Tl[(size_t)n * Kdim + k0 + tx] = ll;
        }
    }
}

// ================= embedding + positional encoding =================
__global__ void embed_kernel(const int* __restrict__ x, const float* __restrict__ emb,
                             bf16* __restrict__ outH, bf16* __restrict__ outL) {
    int t = blockIdx.x;
    int s = t % NS;
    int tok = x[t];
    for (int d = threadIdx.x; d < DMODEL; d += blockDim.x) {
        int j = d >> 1;
        float ang = (float)s * powf(10000.0f, -(2.0f*(float)j)/(float)DMODEL);
        float pe = (d & 1) ? cosf(ang) : sinf(ang);
        float v = emb[tok*DMODEL + d] + pe;
        bf16 hh, ll; split2(v, hh, ll);
        outH[t*DMODEL + d] = hh; outL[t*DMODEL + d] = ll;
    }
}

// ================= split-bf16 HMMA GEMM (K-chunk 32, templated stages) ========
#define NCHUNK   16
#define STRIDE   40
#define TILE_A   (128*STRIDE*2)
template<int NT, int STAGES> struct TileCfg {
    static const int TB  = NT*STRIDE*2;
    static const int BUF = 2*TILE_A + 2*TB;
    static const int SMEM = STAGES*BUF;
    static const int NP  = NT/32;
};

template<int NT, int STAGES>
__device__ __forceinline__ void load_tiles(
    const bf16* __restrict__ Ah, const bf16* __restrict__ Al,
    const bf16* __restrict__ Bh, const bf16* __restrict__ Bl,
    int M, int N, int m0, int n0, int ch, uint32_t sbuf, int tid)
{
    typedef TileCfg<NT, STAGES> TC;
    {
        const int row = tid >> 1;
        const int qd  = (tid & 1) * 2;
        const uint32_t sof = sbuf + (uint32_t)(row*STRIDE + qd*8) * 2;
        bool ok = (m0 + row) < M;
        const bf16* pa = Ah + (size_t)(m0 + row) * 512 + ch*32 + qd*8;
        const bf16* pl = Al + (size_t)(m0 + row) * 512 + ch*32 + qd*8;
        cp16(sof,                pa,     ok);
        cp16(sof + 16,           pa + 8, ok);
        cp16(sof + TILE_A,       pl,     ok);
        cp16(sof + TILE_A + 16,  pl + 8, ok);
    }
    if (NT == 128) {
        const int row = tid >> 1;
        const int qd  = (tid & 1) * 2;
        const uint32_t sof = sbuf + 2*TILE_A + (uint32_t)(row*STRIDE + qd*8) * 2;
        bool ok = (n0 + row) < N;
        const bf16* pb = Bh + (size_t)(n0 + row) * 512 + ch*32 + qd*8;
        const bf16* pl = Bl + (size_t)(n0 + row) * 512 + ch*32 + qd*8;
        cp16(sof,            pb,     ok);
        cp16(sof + 16,       pb + 8, ok);
        cp16(sof + TC::TB,       pl,     ok);
        cp16(sof + TC::TB + 16,  pl + 8, ok);
    } else {
        const int row = tid >> 2;
        const int qd  = tid & 3;
        const uint32_t sof = sbuf + 2*TILE_A + (uint32_t)(row*STRIDE + qd*8) * 2;
        bool ok = (n0 + row) < N;
        cp16(sof,            Bh + (size_t)(n0 + row) * 512 + ch*32 + qd*8, ok);
        cp16(sof + TC::TB,   Bl + (size_t)(n0 + row) * 512 + ch*32 + qd*8, ok);
    }
}

template<int NT, int STAGES>
__device__ void gemm_core(const bf16* __restrict__ Ah, const bf16* __restrict__ Al,
                          const bf16* __restrict__ Bh, const bf16* __restrict__ Bl,
                          float* __restrict__ C, bf16* __restrict__ Ch, bf16* __restrict__ Cl,
                          int M, int N,
                          const float* __restrict__ rowBias, const float* __restrict__ colBias)
{
    typedef TileCfg<NT, STAGES> TC;
    extern __shared__ char smem[];
    const uint32_t sb = smem_to_u32(smem);
    const int tid = threadIdx.x, wid = tid >> 5, lane = tid & 31;
    const int wm = wid & 3, wn = wid >> 2;
    const int m0 = blockIdx.y * 128, n0 = blockIdx.x * NT;
    const int NP = TC::NP;
    const int BUF = TC::BUF;
    const int TB = TC::TB;

    float acc[2][2*TC::NP][4];
    #pragma unroll
    for (int i = 0; i < 2; i++)
        #pragma unroll
        for (int j = 0; j < 2*NP; j++)
            #pragma unroll
            for (int e = 0; e < 4; e++) acc[i][j][e] = 0.f;

    #pragma unroll
    for (int s = 0; s < STAGES-1; s++) {
        load_tiles<NT, STAGES>(Ah, Al, Bh, Bl, M, N, m0, n0, s, sb + s*BUF, tid);
        CP_COMMIT();
    }

    int cur = 0;
    const int aRow = (lane & 15);
    const int aCol = (lane >> 4) << 3;
    const int bRow = (lane & 7) + (((lane >> 4) & 1) << 3);
    const int bCol = ((lane >> 3) & 1) << 3;

    #pragma unroll 1
    for (int ch = 0; ch < NCHUNK; ch++) {
        if (STAGES == 3 && ch < NCHUNK-1) { CP_WAIT1(); } else { CP_WAIT0(); }
        __syncthreads();
        if (ch + STAGES - 1 < NCHUNK) {
            int nb = cur + STAGES - 1; if (nb >= STAGES) nb -= STAGES;
            load_tiles<NT, STAGES>(Ah, Al, Bh, Bl, M, N, m0, n0, ch + STAGES - 1, sb + nb*BUF, tid);
            CP_COMMIT();
        }
        const uint32_t sAh = sb + cur*BUF;
        const uint32_t sAl = sAh + TILE_A;
        const uint32_t sBh = sAh + 2*TILE_A;
        const uint32_t sBl = sBh + TB;

        #pragma unroll
        for (int k16 = 0; k16 < 32; k16 += 16) {
            uint32_t ah[8], al[8];
            uint32_t bh[TC::NP][4], bl[TC::NP][4];
            {
                uint32_t a0 = (uint32_t)((wm*32 + aRow)*STRIDE + k16 + aCol) * 2;
                uint32_t a1 = (uint32_t)((wm*32 + 16 + aRow)*STRIDE + k16 + aCol) * 2;
                ldm4(sAh + a0, ah);  ldm4(sAh + a1, ah + 4);
                ldm4(sAl + a0, al);  ldm4(sAl + a1, al + 4);
            }
            #pragma unroll
            for (int np = 0; np < NP; np++) {
                const int nb2 = wn*(NT/2) + np*16;
                const uint32_t boff = (uint32_t)((nb2 + bRow)*STRIDE + k16 + bCol) * 2;
                ldm4(sBh + boff, bh[np]);
                ldm4(sBl + boff, bl[np]);
            }
            #pragma unroll
            for (int np = 0; np < NP; np++)
                #pragma unroll
                for (int mi = 0; mi < 2; mi++) {
                    mma16816(acc[mi][np*2],     ah + 4*mi, bh[np][0], bh[np][1]);
                    mma16816(acc[mi][np*2 + 1], ah + 4*mi, bh[np][2], bh[np][3]);
                }
            #pragma unroll
            for (int np = 0; np < NP; np++)
                #pragma unroll
                for (int mi = 0; mi < 2; mi++) {
                    mma16816(acc[mi][np*2],     ah + 4*mi, bl[np][0], bl[np][1]);
                    mma16816(acc[mi][np*2 + 1], ah + 4*mi, bl[np][2], bl[np][3]);
                }
            #pragma unroll
            for (int np = 0; np < NP; np++)
                #pragma unroll
                for (int mi = 0; mi < 2; mi++) {
                    mma16816(acc[mi][np*2],     al + 4*mi, bh[np][0], bh[np][1]);
                    mma16816(acc[mi][np*2 + 1], al + 4*mi, bh[np][2], bh[np][3]);
                }
        }
        cur++; if (cur == STAGES) cur = 0;
    }

    // epilogue
    const int r0 = m0 + wm*32 + (lane >> 2);
    const int c0 = n0 + wn*(NT/2) + (lane & 3) * 2;
    #pragma unroll
    for (int mi = 0; mi < 2; mi++) {
        #pragma unroll
        for (int na = 0; na < 2*NP; na++) {
            const int col = c0 + (na >> 1)*16 + (na & 1)*8;
            #pragma unroll
            for (int e = 0; e < 4; e++) {
                const int r = r0 + mi*16 + ((e >> 1) << 3);
                const int c = col + (e & 1);
                if (r >= M || c >= N) continue;
                float v = acc[mi][na][e];
                if (rowBias) v += rowBias[(size_t)(r >> 6) * N + c];
                if (colBias) v += colBias[c];
                if (C) C[(size_t)r * N + c] = v;
                if (Ch) {
                    bf16 hh, ll; split2(v, hh, ll);
                    Ch[(size_t)r * N + c] = hh;
                    Cl[(size_t)r * N + c] = ll;
                }
            }
        }
    }
}

#define SMEM64  (TileCfg<64,3>::SMEM)     // 92160 B
#define SMEM128 (TileCfg<128,2>::SMEM)    // 81920 B

__global__ void __launch_bounds__(256, 2) gemm_plain64(
    const bf16* Ah, const bf16* Al, const bf16* Bh, const bf16* Bl,
    float* C, bf16* Ch, bf16* Cl, int M, int N,
    const float* rowBias, const float* colBias) {
    gemm_core<64,3>(Ah, Al, Bh, Bl, C, Ch, Cl, M, N, rowBias, colBias);
}

__global__ void __launch_bounds__(256, 2) gemm_final128(
    const bf16* Ah, const bf16* Al, const bf16* Bh, const bf16* Bl,
    float* C, int M, int N, const float* colBias) {
    gemm_core<128,2>(Ah, Al, Bh, Bl, C, nullptr, nullptr, M, N, nullptr, colBias);
}

// layer-0 QKV from embedding activations (original weights)
__global__ void __launch_bounds__(256, 2) gemm_qkv3(
    const bf16* Ah, const bf16* Al, const bf16* wTH, const bf16* wTL,
    float* q, float* k, float* v) {
    const int z = blockIdx.z;
    const size_t off = (size_t)z*LLAYERS * WSZ;
    float* C = (z == 0) ? q : (z == 1) ? k : v;
    gemm_core<64,3>(Ah, Al, wTH + off, wTL + off, C, nullptr, nullptr, NTOK, DMODEL, nullptr, nullptr);
}

// combined QKV for layer l+1: qkv = ao_c @ (Wo_c[l] @ W{q,k,v}_s[l+1])
__global__ void __launch_bounds__(256, 2) gemm_qkv3c(
    const bf16* Ah, const bf16* Al, const bf16* WcH, const bf16* WcL, int l,
    float* q, float* k, float* v) {
    const int z = blockIdx.z;
    const size_t off = ((size_t)(l*3 + z)) * WSZ;
    float* C = (z == 0) ? q : (z == 1) ? k : v;
    gemm_core<64,3>(Ah, Al, WcH + off, WcL + off, C, nullptr, nullptr, NTOK, DMODEL, nullptr, nullptr);
}

// WscT[l] = (Wo_s[l] @ Wq_c[l])^T
__global__ void __launch_bounds__(256, 2) gemm_wsc6(
    const bf16* wTH, const bf16* wTL, const bf16* WosH, const bf16* WosL,
    bf16* wscH, bf16* wscL) {
    const int l = blockIdx.z;
    const size_t aoff = ((size_t)4*LLAYERS + l) * WSZ;
    const size_t boff = (size_t)l * WSZ;
    gemm_core<64,3>(wTH + aoff, wTL + aoff, WosH + boff, WosL + boff,
                    nullptr, wscH + boff, wscL + boff, DMODEL, DMODEL, nullptr, nullptr);
}

// Wcb[l*3+m] = (Wo_c[l] @ W{q,k,v}_s[l+1])^T
__global__ void __launch_bounds__(256, 2) gemm_comb15(
    const bf16* wTH, const bf16* wTL, const bf16* WocH, const bf16* WocL,
    bf16* WcH, bf16* WcL) {
    const int z = blockIdx.z, l = z / 3, m = z % 3;
    const size_t aoff = ((size_t)m*LLAYERS + (l+1)) * WSZ;
    const size_t boff = (size_t)l * WSZ;
    gemm_core<64,3>(wTH + aoff, wTL + aoff, WocH + boff, WocL + boff,
                    nullptr, WcH + (size_t)z*WSZ, WcL + (size_t)z*WSZ, DMODEL, DMODEL, nullptr, nullptr);
}

// WfC = (Wo_c[5] @ Wf)^T [10000, 512]
__global__ void __launch_bounds__(256, 2) gemm_wfc(
    const bf16* wfTH, const bf16* wfTL, const bf16* WocH, const bf16* WocL,
    bf16* wfcH, bf16* wfcL) {
    const size_t boff = (size_t)(LLAYERS-1) * WSZ;
    gemm_core<64,3>(wfTH, wfTL, WocH + boff, WocL + boff,
                    nullptr, wfcH, wfcL, NVOCAB, DMODEL, nullptr, nullptr);
}

__global__ void __launch_bounds__(256, 2) gemm_cross2(
    const bf16* KinH, const bf16* KinL, const bf16* VinH, const bf16* VinL,
    const bf16* wTH, const bf16* wTL, int l, float* kc, float* vc) {
    const int kv = blockIdx.z;
    const size_t woff = ((size_t)(6 + kv)*LLAYERS + l) * WSZ;
    gemm_core<128,2>(kv ? VinH : KinH, kv ? VinL : KinL, wTH + woff, wTL + woff,
                     kv ? vc : kc, nullptr, nullptr, NCTOK, DMODEL, nullptr, nullptr);
}

__global__ void __launch_bounds__(256, 2) gemm_gq6(
    const bf16* gH, const bf16* gL, const bf16* wTH, const bf16* wTL, float* gq) {
    const int l = blockIdx.z;
    const size_t woff = ((size_t)5*LLAYERS + l) * WSZ;
    gemm_core<64,3>(gH, gL, wTH + woff, wTL + woff,
                    gq + (size_t)l*NB*DMODEL, nullptr, nullptr, NB, DMODEL, nullptr, nullptr);
}

// ================= fused attention v2 (vectorized fp32), writes hi/lo ==========
// smem: Qs[64][68], Ks[64][68], VsT[64][68] (d-major), Ps[8][8][64]
#define ATTN_SMEM_FLOATS (3*64*68 + 8*512)
template<bool CAUSAL>
__global__ void attn_kernel(const float* __restrict__ Q, const float* __restrict__ Kb,
                            const float* __restrict__ Vb,
                            bf16* __restrict__ Oh, bf16* __restrict__ Ol,
                            int skeys, int kvTokens) {
    extern __shared__ float sm[];
    float* Qs  = sm;
    float* Ks  = sm + 64*68;
    float* VsT = sm + 2*64*68;
    float* Ps  = sm + 3*64*68;

    const int b = blockIdx.x / NH, h = blockIdx.x % NH;
    const int tid = threadIdx.x, w = tid >> 5, lane = tid & 31;

    // Q fill (vectorized)
    for (int i = tid; i < 64*16; i += 256) {
        int r = i >> 4, c4 = (i & 15) * 4;
        float4 qv = *(const float4*)&Q[(size_t)(b*NS + r)*DMODEL + h*HD + c4];
        *(float4*)&Qs[r*68 + c4] = qv;
    }
    float mrow[8], lrow[8], a0[8], a1[8];
    #pragma unroll
    for (int i = 0; i < 8; i++) { mrow[i] = -1e30f; lrow[i] = 0.f; a0[i] = 0.f; a1[i] = 0.f; }
    __syncthreads();

    const int nch = (skeys + 63) >> 6;
    for (int ch = 0; ch < nch; ch++) {
        const int kb = ch * 64;
        const int cnt = min(64, skeys - kb);
        // K fill: row-major, coalesced float4
        for (int i = tid; i < 64*16; i += 256) {
            int r = i >> 4, c4 = (i & 15) * 4;
            float4 kv = make_float4(0.f,0.f,0.f,0.f);
            if (r < cnt)
                kv = *(const float4*)&Kb[(size_t)(b*kvTokens + kb + r)*DMODEL + h*HD + c4];
            *(float4*)&Ks[r*68 + c4] = kv;
        }
        // V fill: transposed (VsT[d][key]); c-major thread mapping keeps stores conflict-free
        for (int i = tid; i < 64*16; i += 256) {
            int c4 = (i >> 6) * 4, r = i & 63;
            float4 vv = make_float4(0.f,0.f,0.f,0.f);
            if (r < cnt)
                vv = *(const float4*)&Vb[(size_t)(b*kvTokens + kb + r)*DMODEL + h*HD + c4];
            VsT[(c4+0)*68 + r] = vv.x;
            VsT[(c4+1)*68 + r] = vv.y;
            VsT[(c4+2)*68 + r] = vv.z;
            VsT[(c4+3)*68 + r] = vv.w;
        }
        __syncthreads();

        // ---- phase 1: scores (vectorized over d) ----
        float d0[8], d1[8];
        #pragma unroll
        for (int i = 0; i < 8; i++) { d0[i] = 0.f; d1[i] = 0.f; }
        #pragma unroll 4
        for (int d4 = 0; d4 < 64; d4 += 4) {
            float4 k0 = *(const float4*)&Ks[lane*68 + d4];
            float4 k1 = *(const float4*)&Ks[(lane+32)*68 + d4];
            #pragma unroll
            for (int rr = 0; rr < 8; rr++) {
                float4 qv = *(const float4*)&Qs[(w*8 + rr)*68 + d4];
                d0[rr] += qv.x*k0.x + qv.y*k0.y + qv.z*k0.z + qv.w*k0.w;
                d1[rr] += qv.x*k1.x + qv.y*k1.y + qv.z*k1.z + qv.w*k1.w;
            }
        }

        // ---- per-row online softmax ----
        #pragma unroll
        for (int rr = 0; rr < 8; rr++) {
            const int r = w*8 + rr;
            float s0 = d0[rr] * 0.125f, s1 = d1[rr] * 0.125f;
            bool v0 = (lane      < cnt) && (!CAUSAL || (kb + lane)      <= r);
            bool v1 = (lane + 32 < cnt) && (!CAUSAL || (kb + lane + 32) <= r);
            if (!v0) s0 = -1e30f;
            if (!v1) s1 = -1e30f;
            float cm = fmaxf(s0, s1);
            #pragma unroll
            for (int o = 16; o > 0; o >>= 1) cm = fmaxf(cm, __shfl_xor_sync(0xffffffffu, cm, o));
            float nm = fmaxf(mrow[rr], cm);
            float corr = __expf(mrow[rr] - nm);
            float p0 = v0 ? __expf(s0 - nm) : 0.f;
            float p1 = v1 ? __expf(s1 - nm) : 0.f;
            float ps = p0 + p1;
            #pragma unroll
            for (int o = 16; o > 0; o >>= 1) ps += __shfl_xor_sync(0xffffffffu, ps, o);
            lrow[rr] = lrow[rr]*corr + ps;
            mrow[rr] = nm;
            a0[rr] *= corr; a1[rr] *= corr;
            Ps[w*512 + rr*64 + lane]      = p0;
            Ps[w*512 + rr*64 + lane + 32] = p1;
        }
        __syncwarp();

        // ---- phase 2: P @ V (vectorized over keys via VsT) ----
        #pragma unroll 4
        for (int kk4 = 0; kk4 < 64; kk4 += 4) {
            float4 v0 = *(const float4*)&VsT[lane*68 + kk4];
            float4 v1 = *(const float4*)&VsT[(lane+32)*68 + kk4];
            #pragma unroll
            for (int rr = 0; rr < 8; rr++) {
                float4 p = *(const float4*)&Ps[w*512 + rr*64 + kk4];
                a0[rr] += p.x*v0.x + p.y*v0.y + p.z*v0.z + p.w*v0.w;
                a1[rr] += p.x*v1.x + p.y*v1.y + p.z*v1.z + p.w*v1.w;
            }
        }
        __syncwarp();
        __syncthreads();
    }
    #pragma unroll
    for (int rr = 0; rr < 8; rr++) {
        int r = w*8 + rr;
        float inv = 1.0f / lrow[rr];
        size_t o = (size_t)(b*NS + r)*DMODEL + h*HD;
        float v0 = a0[rr] * inv, v1 = a1[rr] * inv;
        bf16 hh, ll;
        split2(v0, hh, ll); Oh[o + lane]      = hh; Ol[o + lane]      = ll;
        split2(v1, hh, ll); Oh[o + lane + 32] = hh; Ol[o + lane + 32] = ll;
    }
}

// ================= final row softmax over VOCAB (in-place) =================
__global__ void softmax_kernel(float* __restrict__ out) {
    __shared__ float buf[NVOCAB];
    __shared__ float red[8];
    const int tid = threadIdx.x, w = tid >> 5, lane = tid & 31;
    float* p = out + (size_t)blockIdx.x * NVOCAB;

    float mx = -1e30f;
    for (int i = tid; i < NVOCAB; i += 256) { float v = p[i]; buf[i] = v; mx = fmaxf(mx, v); }
    #pragma unroll
    for (int o = 16; o > 0; o >>= 1) mx = fmaxf(mx, __shfl_xor_sync(0xffffffffu, mx, o));
    if (lane == 0) red[w] = mx;
    __syncthreads();
    mx = red[0];
    #pragma unroll
    for (int i = 1; i < 8; i++) mx = fmaxf(mx, red[i]);
    __syncthreads();

    float sum = 0.f;
    for (int i = tid; i < NVOCAB; i += 256) { float e = __expf(buf[i] - mx); buf[i] = e; sum += e; }
    #pragma unroll
    for (int o = 16; o > 0; o >>= 1) sum += __shfl_xor_sync(0xffffffffu, sum, o);
    if (lane == 0) red[w] = sum;
    __syncthreads();
    sum = 0.f;
    #pragma unroll
    for (int i = 0; i < 8; i++) sum += red[i];
    float inv = 1.0f / sum;
    for (int i = tid; i < NVOCAB; i += 256) p[i] = buf[i] * inv;
}

// ================= host launcher =================
extern "C" void kernel_launch(void* const* d_in, const int* in_sizes, int n_in,
                              void* d_out, int out_size) {
    const int*   x   = (const int*)  d_in[0];
    const float* Kin = (const float*)d_in[1];
    const float* Vin = (const float*)d_in[2];
    const float* g   = (const float*)d_in[3];
    int i = 4;
    if (i < n_in && in_sizes[i] == 1) i++;
    const float* emb  = (const float*)d_in[i++];
    const float* Wq_s = (const float*)d_in[i++];
    const float* Wk_s = (const float*)d_in[i++];
    const float* Wv_s = (const float*)d_in[i++];
    const float* Wo_s = (const float*)d_in[i++];
    const float* Wq_c = (const float*)d_in[i++];
    const float* Wg_c = (const float*)d_in[i++];
    const float* Wk_c = (const float*)d_in[i++];
    const float* Wv_c = (const float*)d_in[i++];
    const float* Wo_c = (const float*)d_in[i++];
    const float* Wf   = (const float*)d_in[i++];
    const float* bf   = (const float*)d_in[i++];

    bf16 *actH, *actL, *aoH, *aoL, *KinH, *KinL, *VinH, *VinL, *gH, *gL;
    bf16 *wTH, *wTL, *wfTH, *wfTL, *WosH, *WosL, *WocH, *WocL;
    bf16 *wscH, *wscL, *wcbH, *wcbL, *wfcH, *wfcL;
    float *q, *k, *v, *kc, *vc, *gq;
    cudaGetSymbolAddress((void**)&actH, g_actH);  cudaGetSymbolAddress((void**)&actL, g_actL);
    cudaGetSymbolAddress((void**)&aoH,  g_aoH);   cudaGetSymbolAddress((void**)&aoL,  g_aoL);
    cudaGetSymbolAddress((void**)&KinH, g_KinH);  cudaGetSymbolAddress((void**)&KinL, g_KinL);
    cudaGetSymbolAddress((void**)&VinH, g_VinH);  cudaGetSymbolAddress((void**)&VinL, g_VinL);
    cudaGetSymbolAddress((void**)&gH,   g_gH);    cudaGetSymbolAddress((void**)&gL,   g_gL);
    cudaGetSymbolAddress((void**)&wTH,  g_wTH);   cudaGetSymbolAddress((void**)&wTL,  g_wTL);
    cudaGetSymbolAddress((void**)&wfTH, g_wfTH);  cudaGetSymbolAddress((void**)&wfTL, g_wfTL);
    cudaGetSymbolAddress((void**)&WosH, g_WosH);  cudaGetSymbolAddress((void**)&WosL, g_WosL);
    cudaGetSymbolAddress((void**)&WocH, g_WocH);  cudaGetSymbolAddress((void**)&WocL, g_WocL);
    cudaGetSymbolAddress((void**)&wscH, g_wscH);  cudaGetSymbolAddress((void**)&wscL, g_wscL);
    cudaGetSymbolAddress((void**)&wcbH, g_wcbH);  cudaGetSymbolAddress((void**)&wcbL, g_wcbL);
    cudaGetSymbolAddress((void**)&wfcH, g_wfcH);  cudaGetSymbolAddress((void**)&wfcL, g_wfcL);
    cudaGetSymbolAddress((void**)&q,  g_q);  cudaGetSymbolAddress((void**)&k, g_k);
    cudaGetSymbolAddress((void**)&v,  g_v);
    cudaGetSymbolAddress((void**)&kc, g_kc); cudaGetSymbolAddress((void**)&vc, g_vc);
    cudaGetSymbolAddress((void**)&gq, g_gq);

    static cudaStream_t sAux = nullptr;
    static cudaEvent_t eFork = nullptr, eWf = nullptr, ePre = nullptr, eComb = nullptr, eCross[LLAYERS];
    if (!sAux) {
        cudaStreamCreateWithFlags(&sAux, cudaStreamNonBlocking);
        cudaEventCreateWithFlags(&eFork, cudaEventDisableTiming);
        cudaEventCreateWithFlags(&eWf,   cudaEventDisableTiming);
        cudaEventCreateWithFlags(&ePre,  cudaEventDisableTiming);
        cudaEventCreateWithFlags(&eComb, cudaEventDisableTiming);
        for (int l = 0; l < LLAYERS; l++)
            cudaEventCreateWithFlags(&eCross[l], cudaEventDisableTiming);
    }

    const int ATTN_SMEM = ATTN_SMEM_FLOATS * (int)sizeof(float);
    cudaFuncSetAttribute(attn_kernel<true>,  cudaFuncAttributeMaxDynamicSharedMemorySize, ATTN_SMEM);
    cudaFuncSetAttribute(attn_kernel<false>, cudaFuncAttributeMaxDynamicSharedMemorySize, ATTN_SMEM);
    cudaFuncSetAttribute(gemm_plain64,  cudaFuncAttributeMaxDynamicSharedMemorySize, SMEM64);
    cudaFuncSetAttribute(gemm_qkv3,     cudaFuncAttributeMaxDynamicSharedMemorySize, SMEM64);
    cudaFuncSetAttribute(gemm_qkv3c,    cudaFuncAttributeMaxDynamicSharedMemorySize, SMEM64);
    cudaFuncSetAttribute(gemm_gq6,      cudaFuncAttributeMaxDynamicSharedMemorySize, SMEM64);
    cudaFuncSetAttribute(gemm_wsc6,     cudaFuncAttributeMaxDynamicSharedMemorySize, SMEM64);
    cudaFuncSetAttribute(gemm_comb15,   cudaFuncAttributeMaxDynamicSharedMemorySize, SMEM64);
    cudaFuncSetAttribute(gemm_wfc,      cudaFuncAttributeMaxDynamicSharedMemorySize, SMEM64);
    cudaFuncSetAttribute(gemm_cross2,   cudaFuncAttributeMaxDynamicSharedMemorySize, SMEM128);
    cudaFuncSetAttribute(gemm_final128, cudaFuncAttributeMaxDynamicSharedMemorySize, SMEM128);

    // ---- main stream: weight conversions + input splits ----
    WPtrs wp;
    wp.p[0]=Wq_s; wp.p[1]=Wk_s; wp.p[2]=Wv_s; wp.p[3]=Wo_s; wp.p[4]=Wq_c;
    wp.p[5]=Wg_c; wp.p[6]=Wk_c; wp.p[7]=Wv_c; wp.p[8]=Wo_c;
    wconv_all_kernel<<<dim3(16, 16, 9*LLAYERS), dim3(32, 8)>>>(wp, wTH, wTL);
    split_kernel<<<((int)(LLAYERS*WSZ)/4 + 255)/256, 256>>>(Wo_s, WosH, WosL, (int)(LLAYERS*WSZ));
    split_kernel<<<((int)(LLAYERS*WSZ)/4 + 255)/256, 256>>>(Wo_c, WocH, WocL, (int)(LLAYERS*WSZ));
    split_kernel<<<((int)CSZ/4 + 255)/256, 256>>>(Kin, KinH, KinL, (int)CSZ);
    split_kernel<<<((int)CSZ/4 + 255)/256, 256>>>(Vin, VinH, VinL, (int)CSZ);
    split_kernel<<<(NB*DMODEL/4 + 255)/256, 256>>>(g, gH, gL, NB*DMODEL);

    // ---- fork aux stream ----
    cudaEventRecord(eFork, 0);
    cudaStreamWaitEvent(sAux, eFork, 0);
    gemm_wsc6<<<dim3(8, 4, LLAYERS), 256, SMEM64, sAux>>>(wTH, wTL, WosH, WosL, wscH, wscL);
    gemm_gq6 <<<dim3(8, 1, LLAYERS), 256, SMEM64, sAux>>>(gH, gL, wTH, wTL, gq);
    cudaEventRecord(ePre, sAux);
    gemm_cross2<<<dim3(4, NCTOK/128, 2), 256, SMEM128, sAux>>>(
        KinH, KinL, VinH, VinL, wTH, wTL, 0, kc, vc);
    cudaEventRecord(eCross[0], sAux);
    gemm_comb15<<<dim3(8, 4, 15), 256, SMEM64, sAux>>>(wTH, wTL, WocH, WocL, wcbH, wcbL);
    cudaEventRecord(eComb, sAux);
    for (int l = 1; l < LLAYERS; l++) {
        gemm_cross2<<<dim3(4, NCTOK/128, 2), 256, SMEM128, sAux>>>(
            KinH, KinL, VinH, VinL, wTH, wTL, l,
            kc + (size_t)l*CSZ, vc + (size_t)l*CSZ);
        cudaEventRecord(eCross[l], sAux);
    }
    wconv_kernel<<<dim3((NVOCAB + 31)/32, 16, 1), dim3(32, 8), 0, sAux>>>(
        Wf, wfTH, wfTL, DMODEL, NVOCAB);
    gemm_wfc<<<dim3(8, (NVOCAB + 127)/128), 256, SMEM64, sAux>>>(
        wfTH, wfTL, WocH, WocL, wfcH, wfcL);
    cudaEventRecord(eWf, sAux);

    // ---- main stream: embedding + layer loop ----
    embed_kernel<<<NTOK, 128>>>(x, emb, actH, actL);
    cudaStreamWaitEvent(0, ePre, 0);
    gemm_qkv3<<<dim3(8, NTOK/128, 3), 256, SMEM64>>>(actH, actL, wTH, wTL, q, k, v);

    for (int l = 0; l < LLAYERS; l++) {
        attn_kernel<true><<<NB*NH, 256, ATTN_SMEM>>>(q, k, v, aoH, aoL, NS, NS);
        gemm_plain64<<<dim3(8, NTOK/128), 256, SMEM64>>>(
            aoH, aoL, wscH + (size_t)l*WSZ, wscL + (size_t)l*WSZ,
            q, nullptr, nullptr, NTOK, DMODEL, gq + (size_t)l*NB*DMODEL, nullptr);
        cudaStreamWaitEvent(0, eCross[l], 0);
        attn_kernel<false><<<NB*NH, 256, ATTN_SMEM>>>(
            q, kc + (size_t)l*CSZ, vc + (size_t)l*CSZ, aoH, aoL, NNR, NNR);
        if (l + 1 < LLAYERS) {
            if (l == 0) cudaStreamWaitEvent(0, eComb, 0);
            gemm_qkv3c<<<dim3(8, NTOK/128, 3), 256, SMEM64>>>(aoH, aoL, wcbH, wcbL, l, q, k, v);
        }
    }

    // ---- final: logits = ao_c @ (Wo_c[5] @ Wf) + bf ----
    cudaStreamWaitEvent(0, eWf, 0);
    gemm_final128<<<dim3((NVOCAB + 127)/128, NTOK/128), 256, SMEM128>>>(
        aoH, aoL, wfcH, wfcL, (float*)d_out, NTOK, NVOCAB, bf);
    softmax_kernel<<<NTOK, 256>>>((float*)d_out);
}